// round 7
// baseline (speedup 1.0000x reference)
#include <cuda_runtime.h>
#include <cstdint>
#include <math.h>

#define B_   16
#define N_   1024
#define D_   1024
#define H_   8
#define HD_  128
#define M_TOT (B_*N_)               /* 16384 */
#define SCALE_ 0.08838834764831845f /* 1/sqrt(128) */
#define NEG_   (-1.0e30f)

// -------- scratch (device globals; allocation is forbidden) --------
__device__ float g_q[(size_t)M_TOT * D_];
__device__ float g_k[(size_t)M_TOT * D_];
__device__ float g_v[(size_t)M_TOT * D_];
__device__ float g_att[(size_t)M_TOT * D_];

// -------- tf32 helpers --------
__device__ __forceinline__ unsigned f2tf(float x) {
    unsigned r; asm("cvt.rna.tf32.f32 %0, %1;" : "=r"(r) : "f"(x)); return r;
}
__device__ __forceinline__ void mma_tf32(float* d, const unsigned* a, const unsigned* b) {
    asm volatile("mma.sync.aligned.m16n8k8.row.col.f32.tf32.tf32.f32 "
        "{%0,%1,%2,%3},{%4,%5,%6,%7},{%8,%9},{%0,%1,%2,%3};"
        : "+f"(d[0]), "+f"(d[1]), "+f"(d[2]), "+f"(d[3])
        : "r"(a[0]), "r"(a[1]), "r"(a[2]), "r"(a[3]), "r"(b[0]), "r"(b[1]));
}

// ============================================================================
// tf32 GEMM with reg-prefetch + double-buffered smem, 1 sync per chunk.
// C[16384 x 1024(/128-tile)] = A @ B + bias.
// headMode=1: B = per-head weights [H][1024][128], col-tile == head
// headMode=0: B = flat [1024][1024]
// Block tile 128x128, BK=16, 256 threads (8 warps, 4x2), warp tile 32x64.
// ============================================================================
__global__ void __launch_bounds__(256, 2) gemm_tf32_kernel(
    const float* __restrict__ A,
    const float* __restrict__ Bsrc,
    const float* __restrict__ bias,
    float* __restrict__ C,
    int headMode)
{
    __shared__ unsigned As[2][128][20];   // stride 20 -> conflict-free A frags
    __shared__ unsigned Bs[2][16][136];   // stride 136 -> conflict-free B frags

    const int rowBase = blockIdx.y * 128;
    const int colTile = blockIdx.x;          // 0..7
    const int colBase = colTile * 128;

    const float* Bp;
    int ldb;
    if (headMode) { Bp = Bsrc + (size_t)colTile * D_ * HD_; ldb = HD_; }
    else          { Bp = Bsrc + colBase;                    ldb = D_;  }

    const int tid  = threadIdx.x;
    const int w    = tid >> 5;
    const int lane = tid & 31;
    const int g    = lane >> 2;
    const int t4   = lane & 3;
    const int warpM = (w & 3) * 32;
    const int warpN = (w >> 2) * 64;

    float c[2][8][4];
    #pragma unroll
    for (int mt = 0; mt < 2; mt++)
        #pragma unroll
        for (int nt = 0; nt < 8; nt++)
            #pragma unroll
            for (int i = 0; i < 4; i++) c[mt][nt][i] = 0.0f;

    const int arow = tid >> 2;          // 0..63  (and +64)
    const int acol = (tid & 3) * 4;
    const int brow = tid >> 4;          // 0..15
    const int bcol = (tid & 15) * 8;

    // prefetch chunk 0
    float4 pa0 = *(const float4*)(A + (size_t)(rowBase + arow) * D_ + acol);
    float4 pa1 = *(const float4*)(A + (size_t)(rowBase + arow + 64) * D_ + acol);
    float4 pb0 = *(const float4*)(Bp + (size_t)brow * ldb + bcol);
    float4 pb1 = *(const float4*)(Bp + (size_t)brow * ldb + bcol + 4);

    for (int cc = 0; cc < 64; cc++) {   // 64 chunks of BK=16
        const int p = cc & 1;
        As[p][arow][acol + 0] = f2tf(pa0.x);
        As[p][arow][acol + 1] = f2tf(pa0.y);
        As[p][arow][acol + 2] = f2tf(pa0.z);
        As[p][arow][acol + 3] = f2tf(pa0.w);
        As[p][arow + 64][acol + 0] = f2tf(pa1.x);
        As[p][arow + 64][acol + 1] = f2tf(pa1.y);
        As[p][arow + 64][acol + 2] = f2tf(pa1.z);
        As[p][arow + 64][acol + 3] = f2tf(pa1.w);
        Bs[p][brow][bcol + 0] = f2tf(pb0.x);
        Bs[p][brow][bcol + 1] = f2tf(pb0.y);
        Bs[p][brow][bcol + 2] = f2tf(pb0.z);
        Bs[p][brow][bcol + 3] = f2tf(pb0.w);
        Bs[p][brow][bcol + 4] = f2tf(pb1.x);
        Bs[p][brow][bcol + 5] = f2tf(pb1.y);
        Bs[p][brow][bcol + 6] = f2tf(pb1.z);
        Bs[p][brow][bcol + 7] = f2tf(pb1.w);
        __syncthreads();

        if (cc < 63) {
            const int k0 = (cc + 1) * 16;
            pa0 = *(const float4*)(A + (size_t)(rowBase + arow) * D_ + k0 + acol);
            pa1 = *(const float4*)(A + (size_t)(rowBase + arow + 64) * D_ + k0 + acol);
            pb0 = *(const float4*)(Bp + (size_t)(k0 + brow) * ldb + bcol);
            pb1 = *(const float4*)(Bp + (size_t)(k0 + brow) * ldb + bcol + 4);
        }

        #pragma unroll
        for (int ks = 0; ks < 2; ks++) {
            const int kk = ks * 8;
            unsigned af[2][4], bf[8][2];
            #pragma unroll
            for (int mt = 0; mt < 2; mt++) {
                int r = warpM + mt * 16 + g;
                af[mt][0] = As[p][r][kk + t4];
                af[mt][1] = As[p][r + 8][kk + t4];
                af[mt][2] = As[p][r][kk + t4 + 4];
                af[mt][3] = As[p][r + 8][kk + t4 + 4];
            }
            #pragma unroll
            for (int nt = 0; nt < 8; nt++) {
                int ncc = warpN + nt * 8 + g;
                bf[nt][0] = Bs[p][kk + t4][ncc];
                bf[nt][1] = Bs[p][kk + t4 + 4][ncc];
            }
            #pragma unroll
            for (int mt = 0; mt < 2; mt++)
                #pragma unroll
                for (int nt = 0; nt < 8; nt++)
                    mma_tf32(c[mt][nt], af[mt], bf[nt]);
        }
    }

    // epilogue
    #pragma unroll
    for (int mt = 0; mt < 2; mt++) {
        int r0 = rowBase + warpM + mt * 16 + g;
        int r1 = r0 + 8;
        #pragma unroll
        for (int nt = 0; nt < 8; nt++) {
            int ncc = colBase + warpN + nt * 8 + t4 * 2;
            float bx = bias[ncc], by = bias[ncc + 1];
            float2 w0 = make_float2(c[mt][nt][0] + bx, c[mt][nt][1] + by);
            float2 w1 = make_float2(c[mt][nt][2] + bx, c[mt][nt][3] + by);
            *(float2*)(C + (size_t)r0 * D_ + ncc) = w0;
            *(float2*)(C + (size_t)r1 * D_ + ncc) = w1;
        }
    }
}

// ============================================================================
// Flash attention, tf32 mma, quartet-parallel softmax, reg-prefetched K/V.
// Block: (b,h) x 64 query rows. 256 threads. 64-key chunks.
// ============================================================================
struct ASmem {
    unsigned Qs[64][132];
    unsigned Ks[64][132];
    unsigned Vs[64][132];
    float    Ps[64][68];
    float    row_max[64];
    float    row_sum[64];
    float    alpha[64];
    int      qm[64];
    int      km[64];
};

__global__ void __launch_bounds__(256) attn_kernel(const int* __restrict__ mask)
{
    extern __shared__ char smem_raw[];
    ASmem& s = *reinterpret_cast<ASmem*>(smem_raw);

    const int bh = blockIdx.y;
    const int b  = bh >> 3;
    const int h  = bh & 7;
    const int rowBase = blockIdx.x * 64;

    const int tid  = threadIdx.x;
    const int w    = tid >> 5;
    const int lane = tid & 31;
    const int g    = lane >> 2;
    const int t4   = lane & 3;
    const int warpMs = (w & 3) * 16;
    const int warpNs = (w >> 2) * 32;
    const int warpNp = (w >> 2) * 64;

    const float* Qg = g_q + ((size_t)(b * N_ + rowBase)) * D_ + h * HD_;
    const float* Kg = g_k + ((size_t)(b * N_)) * D_ + h * HD_;
    const float* Vg = g_v + ((size_t)(b * N_)) * D_ + h * HD_;

    const int lrow = tid >> 2;
    const int lcol = (tid & 3) * 4;

    // load Q tile (tf32-rounded)
    #pragma unroll
    for (int i = 0; i < 8; i++) {
        int cc = lcol + 16 * i;
        float4 v = *(const float4*)(Qg + (size_t)lrow * D_ + cc);
        s.Qs[lrow][cc + 0] = f2tf(v.x);
        s.Qs[lrow][cc + 1] = f2tf(v.y);
        s.Qs[lrow][cc + 2] = f2tf(v.z);
        s.Qs[lrow][cc + 3] = f2tf(v.w);
    }
    if (tid < 64) {
        s.row_max[tid] = -3.0e38f;
        s.row_sum[tid] = 0.0f;
        s.qm[tid] = mask[b * N_ + rowBase + tid];
    }

    float o[8][4];
    #pragma unroll
    for (int nt = 0; nt < 8; nt++)
        #pragma unroll
        for (int i = 0; i < 4; i++) o[nt][i] = 0.0f;

    const int r0 = warpMs + g;
    const int r1 = r0 + 8;

    // prefetch chunk 0
    float4 pk[8], pv[8];
    #pragma unroll
    for (int i = 0; i < 8; i++) {
        int cc = lcol + 16 * i;
        pk[i] = *(const float4*)(Kg + (size_t)lrow * D_ + cc);
        pv[i] = *(const float4*)(Vg + (size_t)lrow * D_ + cc);
    }
    int mpref = (tid < 64) ? mask[b * N_ + tid] : 0;

    for (int c = 0; c < 16; c++) {
        __syncthreads();   // all warps done with previous Ks/Vs/Ps
        #pragma unroll
        for (int i = 0; i < 8; i++) {
            int cc = lcol + 16 * i;
            s.Ks[lrow][cc + 0] = f2tf(pk[i].x);
            s.Ks[lrow][cc + 1] = f2tf(pk[i].y);
            s.Ks[lrow][cc + 2] = f2tf(pk[i].z);
            s.Ks[lrow][cc + 3] = f2tf(pk[i].w);
            s.Vs[lrow][cc + 0] = f2tf(pv[i].x);
            s.Vs[lrow][cc + 1] = f2tf(pv[i].y);
            s.Vs[lrow][cc + 2] = f2tf(pv[i].z);
            s.Vs[lrow][cc + 3] = f2tf(pv[i].w);
        }
        if (tid < 64) s.km[tid] = mpref;
        __syncthreads();

        // prefetch next chunk (hidden under S-mma + softmax + PV)
        if (c < 15) {
            const int kb = (c + 1) * 64;
            #pragma unroll
            for (int i = 0; i < 8; i++) {
                int cc = lcol + 16 * i;
                pk[i] = *(const float4*)(Kg + (size_t)(kb + lrow) * D_ + cc);
                pv[i] = *(const float4*)(Vg + (size_t)(kb + lrow) * D_ + cc);
            }
            if (tid < 64) mpref = mask[b * N_ + kb + tid];
        }

        // ---- S = Q @ K^T ----
        float sf[4][4];
        #pragma unroll
        for (int nt = 0; nt < 4; nt++)
            #pragma unroll
            for (int i = 0; i < 4; i++) sf[nt][i] = 0.0f;

        #pragma unroll
        for (int kk = 0; kk < 128; kk += 8) {
            unsigned af[4];
            af[0] = s.Qs[r0][kk + t4];
            af[1] = s.Qs[r1][kk + t4];
            af[2] = s.Qs[r0][kk + t4 + 4];
            af[3] = s.Qs[r1][kk + t4 + 4];
            #pragma unroll
            for (int nt = 0; nt < 4; nt++) {
                int kcol = warpNs + nt * 8 + g;
                unsigned bf[2];
                bf[0] = s.Ks[kcol][kk + t4];
                bf[1] = s.Ks[kcol][kk + t4 + 4];
                mma_tf32(sf[nt], af, bf);
            }
        }

        // ---- scale + mask -> Ps ----
        const int qm0 = s.qm[r0], qm1 = s.qm[r1];
        #pragma unroll
        for (int nt = 0; nt < 4; nt++) {
            int cb = warpNs + nt * 8 + t4 * 2;
            int k0m = s.km[cb], k1m = s.km[cb + 1];
            s.Ps[r0][cb]     = (qm0 && k0m) ? sf[nt][0] * SCALE_ : NEG_;
            s.Ps[r0][cb + 1] = (qm0 && k1m) ? sf[nt][1] * SCALE_ : NEG_;
            s.Ps[r1][cb]     = (qm1 && k0m) ? sf[nt][2] * SCALE_ : NEG_;
            s.Ps[r1][cb + 1] = (qm1 && k1m) ? sf[nt][3] * SCALE_ : NEG_;
        }
        __syncthreads();

        // ---- online softmax: 4 threads per row ----
        {
            const int r  = tid >> 2;
            const int cb = (tid & 3) * 16;
            float m = s.row_max[r];
            float cm = -3.0e38f;
            #pragma unroll
            for (int c2 = 0; c2 < 16; c2++) cm = fmaxf(cm, s.Ps[r][cb + c2]);
            cm = fmaxf(cm, __shfl_xor_sync(0xFFFFFFFFu, cm, 1));
            cm = fmaxf(cm, __shfl_xor_sync(0xFFFFFFFFu, cm, 2));
            float nm = fmaxf(m, cm);
            float al = __expf(m - nm);
            float sum = 0.0f;
            #pragma unroll
            for (int c2 = 0; c2 < 16; c2++) {
                float p = __expf(s.Ps[r][cb + c2] - nm);
                s.Ps[r][cb + c2] = p;
                sum += p;
            }
            sum += __shfl_xor_sync(0xFFFFFFFFu, sum, 1);
            sum += __shfl_xor_sync(0xFFFFFFFFu, sum, 2);
            if ((tid & 3) == 0) {
                s.row_sum[r] = s.row_sum[r] * al + sum;
                s.row_max[r] = nm;
                s.alpha[r]   = al;
            }
        }
        __syncthreads();

        // ---- O = O*alpha + P @ V ----
        float al0 = s.alpha[r0], al1 = s.alpha[r1];
        #pragma unroll
        for (int nt = 0; nt < 8; nt++) {
            o[nt][0] *= al0; o[nt][1] *= al0;
            o[nt][2] *= al1; o[nt][3] *= al1;
        }
        #pragma unroll
        for (int kk = 0; kk < 64; kk += 8) {
            unsigned af[4];
            af[0] = f2tf(s.Ps[r0][kk + t4]);
            af[1] = f2tf(s.Ps[r1][kk + t4]);
            af[2] = f2tf(s.Ps[r0][kk + t4 + 4]);
            af[3] = f2tf(s.Ps[r1][kk + t4 + 4]);
            #pragma unroll
            for (int nt = 0; nt < 8; nt++) {
                int ec = warpNp + nt * 8 + g;
                unsigned bf[2];
                bf[0] = s.Vs[kk + t4][ec];
                bf[1] = s.Vs[kk + t4 + 4][ec];
                mma_tf32(o[nt], af, bf);
            }
        }
    }

    float inv0 = 1.0f / s.row_sum[r0];
    float inv1 = 1.0f / s.row_sum[r1];
    size_t gr0 = (size_t)(b * N_ + rowBase + r0) * D_;
    size_t gr1 = (size_t)(b * N_ + rowBase + r1) * D_;
    #pragma unroll
    for (int nt = 0; nt < 8; nt++) {
        int cc = h * HD_ + warpNp + nt * 8 + t4 * 2;
        float2 w0 = make_float2(o[nt][0] * inv0, o[nt][1] * inv0);
        float2 w1 = make_float2(o[nt][2] * inv1, o[nt][3] * inv1);
        *(float2*)(g_att + gr0 + cc) = w0;
        *(float2*)(g_att + gr1 + cc) = w1;
    }
}

// ============================================================================
extern "C" void kernel_launch(void* const* d_in, const int* in_sizes, int n_in,
                              void* d_out, int out_size)
{
    const float* x    = (const float*)d_in[0];
    const int*   xm   = (const int*)d_in[1];
    const float* Wq   = (const float*)d_in[2];
    const float* bq   = (const float*)d_in[3];
    const float* Wk   = (const float*)d_in[4];
    const float* bk   = (const float*)d_in[5];
    const float* Wv   = (const float*)d_in[6];
    const float* bv   = (const float*)d_in[7];
    const float* Wfc  = (const float*)d_in[8];
    const float* bfc  = (const float*)d_in[9];
    float* out = (float*)d_out;

    float *qp, *kp, *vp, *ap;
    cudaGetSymbolAddress((void**)&qp, g_q);
    cudaGetSymbolAddress((void**)&kp, g_k);
    cudaGetSymbolAddress((void**)&vp, g_v);
    cudaGetSymbolAddress((void**)&ap, g_att);

    cudaFuncSetAttribute(attn_kernel,
                         cudaFuncAttributeMaxDynamicSharedMemorySize,
                         (int)sizeof(ASmem));

    dim3 gGrid(8, 128);
    gemm_tf32_kernel<<<gGrid, 256>>>(x, Wq, bq, qp, 1);
    gemm_tf32_kernel<<<gGrid, 256>>>(x, Wk, bk, kp, 1);
    gemm_tf32_kernel<<<gGrid, 256>>>(x, Wv, bv, vp, 1);

    dim3 aGrid(N_ / 64, B_ * H_);
    attn_kernel<<<aGrid, 256, sizeof(ASmem)>>>(xm);

    gemm_tf32_kernel<<<gGrid, 256>>>(ap, Wfc, bfc, out, 0);
}

// round 9
// speedup vs baseline: 1.4675x; 1.4675x over previous
#include <cuda_runtime.h>
#include <cstdint>
#include <math.h>

#define B_   16
#define N_   1024
#define D_   1024
#define H_   8
#define HD_  128
#define M_TOT (B_*N_)               /* 16384 */
#define SCALE_ 0.08838834764831845f /* 1/sqrt(128) */
#define NEG_   (-1.0e30f)

// -------- scratch (device globals; allocation is forbidden) --------
__device__ float g_q[(size_t)M_TOT * D_];     // tf32-rounded
__device__ float g_k[(size_t)M_TOT * D_];     // tf32-rounded
__device__ float g_v[(size_t)M_TOT * D_];     // tf32-rounded
__device__ float g_att[(size_t)M_TOT * D_];   // tf32-rounded
__device__ float g_x[(size_t)M_TOT * D_];     // tf32-rounded copy of x
__device__ float g_wq[(size_t)H_ * D_ * HD_]; // tf32-rounded weights
__device__ float g_wk[(size_t)H_ * D_ * HD_];
__device__ float g_wv[(size_t)H_ * D_ * HD_];
__device__ float g_wf[(size_t)D_ * D_];

// -------- helpers --------
__device__ __forceinline__ unsigned f2tf(float x) {
    unsigned r; asm("cvt.rna.tf32.f32 %0, %1;" : "=r"(r) : "f"(x)); return r;
}
__device__ __forceinline__ void mma_tf32(float* d, const unsigned* a, const unsigned* b) {
    asm volatile("mma.sync.aligned.m16n8k8.row.col.f32.tf32.tf32.f32 "
        "{%0,%1,%2,%3},{%4,%5,%6,%7},{%8,%9},{%0,%1,%2,%3};"
        : "+f"(d[0]), "+f"(d[1]), "+f"(d[2]), "+f"(d[3])
        : "r"(a[0]), "r"(a[1]), "r"(a[2]), "r"(a[3]), "r"(b[0]), "r"(b[1]));
}
__device__ __forceinline__ uint32_t smem_u32(const void* p) {
    uint32_t a;
    asm("{ .reg .u64 t; cvta.to.shared.u64 t, %1; cvt.u32.u64 %0, t; }" : "=r"(a) : "l"(p));
    return a;
}
__device__ __forceinline__ void cp16(uint32_t dst, const void* src) {
    asm volatile("cp.async.cg.shared.global [%0], [%1], 16;" :: "r"(dst), "l"(src));
}
#define CP_COMMIT() asm volatile("cp.async.commit_group;" ::: "memory")
#define CP_WAIT0()  asm volatile("cp.async.wait_group 0;" ::: "memory")

// ============================================================================
// Elementwise tf32 rounding pass (operand pre-conversion).
// ============================================================================
__global__ void conv_tf32_kernel(const float4* __restrict__ in,
                                 float4* __restrict__ out, int n4)
{
    int i = blockIdx.x * blockDim.x + threadIdx.x;
    if (i < n4) {
        float4 v = in[i];
        float4 w;
        w.x = __uint_as_float(f2tf(v.x));
        w.y = __uint_as_float(f2tf(v.y));
        w.z = __uint_as_float(f2tf(v.z));
        w.w = __uint_as_float(f2tf(v.w));
        out[i] = w;
    }
}

// ============================================================================
// tf32 GEMM, cp.async double-buffered, operands pre-converted.
// C[16384 x 1024(/128-tile)] = A @ B (+bias). Output tf32-rounded if rndOut.
// headMode=1: B = per-head weights [H][1024][128], col-tile == head
// headMode=0: B = flat [1024][1024]
// Block tile 128x128, BK=16, 256 threads (8 warps, 4x2), warp tile 32x64.
// ============================================================================
__global__ void __launch_bounds__(256, 2) gemm_tf32_kernel(
    const float* __restrict__ A,
    const float* __restrict__ Bsrc,
    const float* __restrict__ bias,
    float* __restrict__ C,
    int headMode, int rndOut)
{
    __shared__ unsigned As[2][128][20];   // tf32 bits, stride 20 conflict-free
    __shared__ unsigned Bs[2][16][136];   // tf32 bits, stride 136 conflict-free

    const int rowBase = blockIdx.y * 128;
    const int colTile = blockIdx.x;          // 0..7
    const int colBase = colTile * 128;

    const float* Bp;
    int ldb;
    if (headMode) { Bp = Bsrc + (size_t)colTile * D_ * HD_; ldb = HD_; }
    else          { Bp = Bsrc + colBase;                    ldb = D_;  }

    const int tid  = threadIdx.x;
    const int w    = tid >> 5;
    const int lane = tid & 31;
    const int g    = lane >> 2;
    const int t4   = lane & 3;
    const int warpM = (w & 3) * 32;
    const int warpN = (w >> 2) * 64;

    float c[2][8][4];
    #pragma unroll
    for (int mt = 0; mt < 2; mt++)
        #pragma unroll
        for (int nt = 0; nt < 8; nt++)
            #pragma unroll
            for (int i = 0; i < 4; i++) c[mt][nt][i] = 0.0f;

    const int arow = tid >> 2;          // 0..63 (and +64)
    const int acol = (tid & 3) * 4;
    const int brow = tid >> 4;          // 0..15
    const int bcol = (tid & 15) * 8;

    const uint32_t asB = smem_u32(&As[0][0][0]);
    const uint32_t bsB = smem_u32(&Bs[0][0][0]);
    const uint32_t dA0 = asB + ((uint32_t)arow * 20 + acol) * 4;
    const uint32_t dA1 = asB + ((uint32_t)(arow + 64) * 20 + acol) * 4;
    const uint32_t dB0 = bsB + ((uint32_t)brow * 136 + bcol) * 4;
    const uint32_t STA = 128 * 20 * 4;   // A stage stride bytes
    const uint32_t STB = 16 * 136 * 4;

    const float* srcA0 = A + (size_t)(rowBase + arow) * D_ + acol;
    const float* srcA1 = A + (size_t)(rowBase + arow + 64) * D_ + acol;
    const float* srcB  = Bp + (size_t)brow * ldb + bcol;

    // prologue: chunk 0 -> stage 0
    cp16(dA0, srcA0);
    cp16(dA1, srcA1);
    cp16(dB0, srcB);
    cp16(dB0 + 16, srcB + 4);
    CP_COMMIT();

    for (int cc = 0; cc < 64; cc++) {   // 64 chunks of BK=16
        const int p = cc & 1;
        CP_WAIT0();
        __syncthreads();

        if (cc < 63) {
            const int k0 = (cc + 1) * 16;
            const uint32_t pn = (cc + 1) & 1;
            cp16(dA0 + pn * STA, srcA0 + k0);
            cp16(dA1 + pn * STA, srcA1 + k0);
            cp16(dB0 + pn * STB, srcB + (size_t)k0 * ldb);
            cp16(dB0 + pn * STB + 16, srcB + (size_t)k0 * ldb + 4);
            CP_COMMIT();
        }

        #pragma unroll
        for (int ks = 0; ks < 2; ks++) {
            const int kk = ks * 8;
            unsigned af[2][4], bf[8][2];
            #pragma unroll
            for (int mt = 0; mt < 2; mt++) {
                int r = warpM + mt * 16 + g;
                af[mt][0] = As[p][r][kk + t4];
                af[mt][1] = As[p][r + 8][kk + t4];
                af[mt][2] = As[p][r][kk + t4 + 4];
                af[mt][3] = As[p][r + 8][kk + t4 + 4];
            }
            #pragma unroll
            for (int nt = 0; nt < 8; nt++) {
                int ncc = warpN + nt * 8 + g;
                bf[nt][0] = Bs[p][kk + t4][ncc];
                bf[nt][1] = Bs[p][kk + t4 + 4][ncc];
            }
            #pragma unroll
            for (int mt = 0; mt < 2; mt++)
                #pragma unroll
                for (int nt = 0; nt < 8; nt++)
                    mma_tf32(c[mt][nt], af[mt], bf[nt]);
        }
        __syncthreads();
    }

    // epilogue
    #pragma unroll
    for (int mt = 0; mt < 2; mt++) {
        int r0 = rowBase + warpM + mt * 16 + g;
        int r1 = r0 + 8;
        #pragma unroll
        for (int nt = 0; nt < 8; nt++) {
            int ncc = colBase + warpN + nt * 8 + t4 * 2;
            float bx = bias[ncc], by = bias[ncc + 1];
            float2 w0 = make_float2(c[mt][nt][0] + bx, c[mt][nt][1] + by);
            float2 w1 = make_float2(c[mt][nt][2] + bx, c[mt][nt][3] + by);
            if (rndOut) {
                w0.x = __uint_as_float(f2tf(w0.x));
                w0.y = __uint_as_float(f2tf(w0.y));
                w1.x = __uint_as_float(f2tf(w1.x));
                w1.y = __uint_as_float(f2tf(w1.y));
            }
            *(float2*)(C + (size_t)r0 * D_ + ncc) = w0;
            *(float2*)(C + (size_t)r1 * D_ + ncc) = w1;
        }
    }
}

// ============================================================================
// Flash attention: tf32 mma, cp.async double-buffered K/V, quartet softmax.
// Block: (b,h) x 64 query rows. 256 threads. 64-key chunks. Inputs pre-tf32.
// ============================================================================
struct ASmem {
    unsigned Qs[2 * 64][132];   // [qrow][e] (2x64 rows layout kept flat 64; see note)
    unsigned Ks[2][64][132];
    unsigned Vs[2][64][132];
    float    Ps[64][68];
    float    row_max[64];
    float    row_sum[64];
    float    alpha[64];
    int      qm[64];
    int      km[64];
};
// NOTE: Qs uses only rows [0,64); declared oversized rows are NOT used.
// (kept to preserve 16B alignment of Ks base; 64*132*4 = 33792 is 16B-aligned,
//  so we actually only need 64 rows — use 64.)

struct ASmem2 {
    unsigned Qs[64][132];
    unsigned Ks[2][64][132];
    unsigned Vs[2][64][132];
    float    Ps[64][68];
    float    row_max[64];
    float    row_sum[64];
    float    alpha[64];
    int      qm[64];
    int      km[64];
};

__global__ void __launch_bounds__(256) attn_kernel(const int* __restrict__ mask)
{
    extern __shared__ char smem_raw[];
    ASmem2& s = *reinterpret_cast<ASmem2*>(smem_raw);

    const int bh = blockIdx.y;
    const int b  = bh >> 3;
    const int h  = bh & 7;
    const int rowBase = blockIdx.x * 64;

    const int tid  = threadIdx.x;
    const int w    = tid >> 5;
    const int lane = tid & 31;
    const int g    = lane >> 2;
    const int t4   = lane & 3;
    const int warpMs = (w & 3) * 16;
    const int warpNs = (w >> 2) * 32;
    const int warpNp = (w >> 2) * 64;

    const float* Qg = g_q + ((size_t)(b * N_ + rowBase)) * D_ + h * HD_;
    const float* Kg = g_k + ((size_t)(b * N_)) * D_ + h * HD_;
    const float* Vg = g_v + ((size_t)(b * N_)) * D_ + h * HD_;

    const int lrow = tid >> 2;          // 0..63
    const int lcol = (tid & 3) * 4;     // +16*i

    // K/V cp.async destination addresses
    const uint32_t ksB = smem_u32(&s.Ks[0][0][0]);
    const uint32_t vsB = smem_u32(&s.Vs[0][0][0]);
    const uint32_t STG_ = 64 * 132 * 4;   // stage stride bytes

    // load Q tile (already tf32 bits in gmem)
    #pragma unroll
    for (int i = 0; i < 8; i++) {
        int cc = lcol + 16 * i;
        float4 v = *(const float4*)(Qg + (size_t)lrow * D_ + cc);
        s.Qs[lrow][cc + 0] = __float_as_uint(v.x);
        s.Qs[lrow][cc + 1] = __float_as_uint(v.y);
        s.Qs[lrow][cc + 2] = __float_as_uint(v.z);
        s.Qs[lrow][cc + 3] = __float_as_uint(v.w);
    }
    if (tid < 64) {
        s.row_max[tid] = -3.0e38f;
        s.row_sum[tid] = 0.0f;
        s.qm[tid] = mask[b * N_ + rowBase + tid];
    }

    float o[8][4];
    #pragma unroll
    for (int nt = 0; nt < 8; nt++)
        #pragma unroll
        for (int i = 0; i < 4; i++) o[nt][i] = 0.0f;

    const int r0 = warpMs + g;
    const int r1 = r0 + 8;

    // prologue: chunk 0 -> stage 0
    #pragma unroll
    for (int i = 0; i < 8; i++) {
        int cc = lcol + 16 * i;
        uint32_t off = ((uint32_t)lrow * 132 + cc) * 4;
        cp16(ksB + off, Kg + (size_t)lrow * D_ + cc);
        cp16(vsB + off, Vg + (size_t)lrow * D_ + cc);
    }
    CP_COMMIT();

    for (int c = 0; c < 16; c++) {
        const int p = c & 1;
        CP_WAIT0();
        __syncthreads();           // stage c ready; prev PV done everywhere

        if (tid < 64) s.km[tid] = mask[b * N_ + c * 64 + tid];

        if (c < 15) {
            const int kb = (c + 1) * 64;
            const uint32_t pn = (c + 1) & 1;
            #pragma unroll
            for (int i = 0; i < 8; i++) {
                int cc = lcol + 16 * i;
                uint32_t off = pn * STG_ + ((uint32_t)lrow * 132 + cc) * 4;
                cp16(ksB + off, Kg + (size_t)(kb + lrow) * D_ + cc);
                cp16(vsB + off, Vg + (size_t)(kb + lrow) * D_ + cc);
            }
            CP_COMMIT();
        }

        // ---- S = Q @ K^T (raw scores -> Ps) ----
        float sf[4][4];
        #pragma unroll
        for (int nt = 0; nt < 4; nt++)
            #pragma unroll
            for (int i = 0; i < 4; i++) sf[nt][i] = 0.0f;

        #pragma unroll
        for (int kk = 0; kk < 128; kk += 8) {
            unsigned af[4];
            af[0] = s.Qs[r0][kk + t4];
            af[1] = s.Qs[r1][kk + t4];
            af[2] = s.Qs[r0][kk + t4 + 4];
            af[3] = s.Qs[r1][kk + t4 + 4];
            #pragma unroll
            for (int nt = 0; nt < 4; nt++) {
                int kcol = warpNs + nt * 8 + g;
                unsigned bf[2];
                bf[0] = s.Ks[p][kcol][kk + t4];
                bf[1] = s.Ks[p][kcol][kk + t4 + 4];
                mma_tf32(sf[nt], af, bf);
            }
        }
        #pragma unroll
        for (int nt = 0; nt < 4; nt++) {
            int cb = warpNs + nt * 8 + t4 * 2;
            s.Ps[r0][cb]     = sf[nt][0];
            s.Ps[r0][cb + 1] = sf[nt][1];
            s.Ps[r1][cb]     = sf[nt][2];
            s.Ps[r1][cb + 1] = sf[nt][3];
        }
        __syncthreads();

        // ---- quartet softmax: 4 threads/row, mask+scale folded in ----
        {
            const int r  = tid >> 2;
            const int cb = (tid & 3) * 16;
            const int qmr = s.qm[r];
            float m = s.row_max[r];
            float tv[16];
            float cm = -3.0e38f;
            #pragma unroll
            for (int c2 = 0; c2 < 16; c2++) {
                float v = (qmr && s.km[cb + c2]) ? s.Ps[r][cb + c2] * SCALE_ : NEG_;
                tv[c2] = v;
                cm = fmaxf(cm, v);
            }
            cm = fmaxf(cm, __shfl_xor_sync(0xFFFFFFFFu, cm, 1));
            cm = fmaxf(cm, __shfl_xor_sync(0xFFFFFFFFu, cm, 2));
            float nm = fmaxf(m, cm);
            float al = __expf(m - nm);
            float sum = 0.0f;
            #pragma unroll
            for (int c2 = 0; c2 < 16; c2++) {
                float pp = __expf(tv[c2] - nm);
                s.Ps[r][cb + c2] = pp;
                sum += pp;
            }
            sum += __shfl_xor_sync(0xFFFFFFFFu, sum, 1);
            sum += __shfl_xor_sync(0xFFFFFFFFu, sum, 2);
            if ((tid & 3) == 0) {
                s.row_sum[r] = s.row_sum[r] * al + sum;
                s.row_max[r] = nm;
                s.alpha[r]   = al;
            }
        }
        __syncthreads();

        // ---- O = O*alpha + P @ V ----
        float al0 = s.alpha[r0], al1 = s.alpha[r1];
        #pragma unroll
        for (int nt = 0; nt < 8; nt++) {
            o[nt][0] *= al0; o[nt][1] *= al0;
            o[nt][2] *= al1; o[nt][3] *= al1;
        }
        #pragma unroll
        for (int kk = 0; kk < 64; kk += 8) {
            unsigned af[4];
            af[0] = f2tf(s.Ps[r0][kk + t4]);
            af[1] = f2tf(s.Ps[r1][kk + t4]);
            af[2] = f2tf(s.Ps[r0][kk + t4 + 4]);
            af[3] = f2tf(s.Ps[r1][kk + t4 + 4]);
            #pragma unroll
            for (int nt = 0; nt < 8; nt++) {
                int ec = warpNp + nt * 8 + g;
                unsigned bf[2];
                bf[0] = s.Vs[p][kk + t4][ec];
                bf[1] = s.Vs[p][kk + t4 + 4][ec];
                mma_tf32(o[nt], af, bf);
            }
        }
    }

    // ---- epilogue: divide, round to tf32 (FC A operand), store ----
    float inv0 = 1.0f / s.row_sum[r0];
    float inv1 = 1.0f / s.row_sum[r1];
    size_t gr0 = (size_t)(b * N_ + rowBase + r0) * D_;
    size_t gr1 = (size_t)(b * N_ + rowBase + r1) * D_;
    #pragma unroll
    for (int nt = 0; nt < 8; nt++) {
        int cc = h * HD_ + warpNp + nt * 8 + t4 * 2;
        float2 w0, w1;
        w0.x = __uint_as_float(f2tf(o[nt][0] * inv0));
        w0.y = __uint_as_float(f2tf(o[nt][1] * inv0));
        w1.x = __uint_as_float(f2tf(o[nt][2] * inv1));
        w1.y = __uint_as_float(f2tf(o[nt][3] * inv1));
        *(float2*)(g_att + gr0 + cc) = w0;
        *(float2*)(g_att + gr1 + cc) = w1;
    }
}

// ============================================================================
extern "C" void kernel_launch(void* const* d_in, const int* in_sizes, int n_in,
                              void* d_out, int out_size)
{
    const float* x    = (const float*)d_in[0];
    const int*   xm   = (const int*)d_in[1];
    const float* Wq   = (const float*)d_in[2];
    const float* bq   = (const float*)d_in[3];
    const float* Wk   = (const float*)d_in[4];
    const float* bk   = (const float*)d_in[5];
    const float* Wv   = (const float*)d_in[6];
    const float* bv   = (const float*)d_in[7];
    const float* Wfc  = (const float*)d_in[8];
    const float* bfc  = (const float*)d_in[9];
    float* out = (float*)d_out;

    float *qp, *kp, *vp, *ap, *xp, *wqp, *wkp, *wvp, *wfp;
    cudaGetSymbolAddress((void**)&qp,  g_q);
    cudaGetSymbolAddress((void**)&kp,  g_k);
    cudaGetSymbolAddress((void**)&vp,  g_v);
    cudaGetSymbolAddress((void**)&ap,  g_att);
    cudaGetSymbolAddress((void**)&xp,  g_x);
    cudaGetSymbolAddress((void**)&wqp, g_wq);
    cudaGetSymbolAddress((void**)&wkp, g_wk);
    cudaGetSymbolAddress((void**)&wvp, g_wv);
    cudaGetSymbolAddress((void**)&wfp, g_wf);

    cudaFuncSetAttribute(attn_kernel,
                         cudaFuncAttributeMaxDynamicSharedMemorySize,
                         (int)sizeof(ASmem2));

    // operand pre-conversion to tf32
    const int XN4 = (M_TOT * D_) / 4;
    const int WN4 = (H_ * D_ * HD_) / 4;
    conv_tf32_kernel<<<(XN4 + 255) / 256, 256>>>((const float4*)x,  (float4*)xp,  XN4);
    conv_tf32_kernel<<<(WN4 + 255) / 256, 256>>>((const float4*)Wq, (float4*)wqp, WN4);
    conv_tf32_kernel<<<(WN4 + 255) / 256, 256>>>((const float4*)Wk, (float4*)wkp, WN4);
    conv_tf32_kernel<<<(WN4 + 255) / 256, 256>>>((const float4*)Wv, (float4*)wvp, WN4);
    conv_tf32_kernel<<<(WN4 + 255) / 256, 256>>>((const float4*)Wfc,(float4*)wfp, WN4);

    dim3 gGrid(8, 128);
    gemm_tf32_kernel<<<gGrid, 256>>>(xp, wqp, bq, qp, 1, 1);
    gemm_tf32_kernel<<<gGrid, 256>>>(xp, wkp, bk, kp, 1, 1);
    gemm_tf32_kernel<<<gGrid, 256>>>(xp, wvp, bv, vp, 1, 1);

    dim3 aGrid(N_ / 64, B_ * H_);
    attn_kernel<<<aGrid, 256, sizeof(ASmem2)>>>(xm);

    gemm_tf32_kernel<<<gGrid, 256>>>(ap, wfp, bfc, out, 0, 0);
}

// round 12
// speedup vs baseline: 2.3707x; 1.6155x over previous
#include <cuda_runtime.h>
#include <cstdint>
#include <math.h>

#define B_   16
#define N_   1024
#define D_   1024
#define H_   8
#define HD_  128
#define M_TOT (B_*N_)               /* 16384 */
#define SCALE_ 0.08838834764831845f /* 1/sqrt(128) */
#define NEG_   (-1.0e30f)

// -------- scratch (device globals; allocation is forbidden) --------
__device__ float g_q[(size_t)M_TOT * D_];     // tf32-rounded
__device__ float g_k[(size_t)M_TOT * D_];     // tf32-rounded
__device__ float g_v[(size_t)M_TOT * D_];     // tf32-rounded
__device__ float g_att[(size_t)M_TOT * D_];   // tf32-rounded
__device__ float g_x[(size_t)M_TOT * D_];     // tf32-rounded copy of x
__device__ float g_wq[(size_t)H_ * D_ * HD_];
__device__ float g_wk[(size_t)H_ * D_ * HD_];
__device__ float g_wv[(size_t)H_ * D_ * HD_];
__device__ float g_wf[(size_t)D_ * D_];
__device__ int   g_idx[B_ * N_];              // per-batch compacted indices
__device__ int   g_cnt[B_];                   // per-batch unmasked count
__device__ float g_vmean[B_ * H_ * HD_];      // mean over ALL keys of v

// -------- helpers --------
__device__ __forceinline__ unsigned f2tf(float x) {
    unsigned r; asm("cvt.rna.tf32.f32 %0, %1;" : "=r"(r) : "f"(x)); return r;
}
__device__ __forceinline__ void mma_tf32(float* d, const unsigned* a, const unsigned* b) {
    asm volatile("mma.sync.aligned.m16n8k8.row.col.f32.tf32.tf32.f32 "
        "{%0,%1,%2,%3},{%4,%5,%6,%7},{%8,%9},{%0,%1,%2,%3};"
        : "+f"(d[0]), "+f"(d[1]), "+f"(d[2]), "+f"(d[3])
        : "r"(a[0]), "r"(a[1]), "r"(a[2]), "r"(a[3]), "r"(b[0]), "r"(b[1]));
}
__device__ __forceinline__ uint32_t smem_u32(const void* p) {
    uint32_t a;
    asm("{ .reg .u64 t; cvta.to.shared.u64 t, %1; cvt.u32.u64 %0, t; }" : "=r"(a) : "l"(p));
    return a;
}
__device__ __forceinline__ void cp16(uint32_t dst, const void* src) {
    asm volatile("cp.async.cg.shared.global [%0], [%1], 16;" :: "r"(dst), "l"(src));
}
#define CP_COMMIT() asm volatile("cp.async.commit_group;" ::: "memory")
#define CP_WAIT0()  asm volatile("cp.async.wait_group 0;" ::: "memory")
#define CP_WAIT1()  asm volatile("cp.async.wait_group 1;" ::: "memory")

// ============================================================================
// Elementwise tf32 rounding pass.
// ============================================================================
__global__ void conv_tf32_kernel(const float4* __restrict__ in,
                                 float4* __restrict__ out, int n4)
{
    int i = blockIdx.x * blockDim.x + threadIdx.x;
    if (i < n4) {
        float4 v = in[i];
        float4 w;
        w.x = __uint_as_float(f2tf(v.x));
        w.y = __uint_as_float(f2tf(v.y));
        w.z = __uint_as_float(f2tf(v.z));
        w.w = __uint_as_float(f2tf(v.w));
        out[i] = w;
    }
}

// ============================================================================
// Per-batch deterministic prefix scan of the mask -> compacted index list.
// grid = B_, block = 1024.
// ============================================================================
__global__ void scan_kernel(const int* __restrict__ mask)
{
    __shared__ int sb[N_];
    const int b = blockIdx.x;
    const int t = threadIdx.x;
    const int m = mask[b * N_ + t];
    sb[t] = m;
    __syncthreads();
    #pragma unroll
    for (int off = 1; off < N_; off <<= 1) {
        int v = (t >= off) ? sb[t - off] : 0;
        __syncthreads();
        sb[t] += v;
        __syncthreads();
    }
    if (m) g_idx[b * N_ + sb[t] - 1] = t;
    if (t == N_ - 1) g_cnt[b] = sb[t];
}

// ============================================================================
// vmean[b][h][e] = (1/N) * sum_n v[b][n][h*128+e]   (tf32-rounded)
// grid = (H_, B_), block = 128.
// ============================================================================
__global__ void vmean_kernel()
{
    const int h = blockIdx.x, b = blockIdx.y, e = threadIdx.x;
    const float* src = g_v + (size_t)b * N_ * D_ + h * HD_ + e;
    float acc = 0.0f;
    for (int n = 0; n < N_; n++) acc += src[(size_t)n * D_];
    g_vmean[(b * H_ + h) * HD_ + e] = __uint_as_float(f2tf(acc * (1.0f / N_)));
}

// ============================================================================
// Fill masked query rows of g_att with the uniform-softmax result (= vmean).
// grid = M_TOT, block = 128.
// ============================================================================
__global__ void fill_kernel(const int* __restrict__ mask)
{
    const int row = blockIdx.x;
    if (mask[row]) return;
    const int b = row >> 10;
    float* dst = g_att + (size_t)row * D_;
    const float* vm = g_vmean + b * H_ * HD_;
    for (int d = threadIdx.x; d < D_; d += 128) dst[d] = vm[d];
}

// ============================================================================
// tf32 GEMM, 3-stage cp.async pipeline, operands pre-converted.
// Block tile 128x128, BK=16, 256 threads (8 warps, 4x2), warp tile 32x64.
// ============================================================================
__global__ void __launch_bounds__(256, 2) gemm_tf32_kernel(
    const float* __restrict__ A,
    const float* __restrict__ Bsrc,
    const float* __restrict__ bias,
    float* __restrict__ C,
    int headMode, int rndOut)
{
    __shared__ unsigned As[3][128][20];
    __shared__ unsigned Bs[3][16][136];

    const int rowBase = blockIdx.y * 128;
    const int colTile = blockIdx.x;
    const int colBase = colTile * 128;

    const float* Bp;
    int ldb;
    if (headMode) { Bp = Bsrc + (size_t)colTile * D_ * HD_; ldb = HD_; }
    else          { Bp = Bsrc + colBase;                    ldb = D_;  }

    const int tid  = threadIdx.x;
    const int w    = tid >> 5;
    const int lane = tid & 31;
    const int g    = lane >> 2;
    const int t4   = lane & 3;
    const int warpM = (w & 3) * 32;
    const int warpN = (w >> 2) * 64;

    float c[2][8][4];
    #pragma unroll
    for (int mt = 0; mt < 2; mt++)
        #pragma unroll
        for (int nt = 0; nt < 8; nt++)
            #pragma unroll
            for (int i = 0; i < 4; i++) c[mt][nt][i] = 0.0f;

    const int arow = tid >> 2;
    const int acol = (tid & 3) * 4;
    const int brow = tid >> 4;
    const int bcol = (tid & 15) * 8;

    const uint32_t asB = smem_u32(&As[0][0][0]);
    const uint32_t bsB = smem_u32(&Bs[0][0][0]);
    const uint32_t dA0 = asB + ((uint32_t)arow * 20 + acol) * 4;
    const uint32_t dA1 = asB + ((uint32_t)(arow + 64) * 20 + acol) * 4;
    const uint32_t dB0 = bsB + ((uint32_t)brow * 136 + bcol) * 4;
    const uint32_t STA = 128 * 20 * 4;
    const uint32_t STB = 16 * 136 * 4;

    const float* srcA0 = A + (size_t)(rowBase + arow) * D_ + acol;
    const float* srcA1 = A + (size_t)(rowBase + arow + 64) * D_ + acol;
    const float* srcB  = Bp + (size_t)brow * ldb + bcol;

    // prologue: chunks 0,1 -> stages 0,1
    #pragma unroll
    for (int pc = 0; pc < 2; pc++) {
        const int k0 = pc * 16;
        cp16(dA0 + pc * STA, srcA0 + k0);
        cp16(dA1 + pc * STA, srcA1 + k0);
        cp16(dB0 + pc * STB, srcB + (size_t)k0 * ldb);
        cp16(dB0 + pc * STB + 16, srcB + (size_t)k0 * ldb + 4);
        CP_COMMIT();
    }

    int p = 0;
    for (int cc = 0; cc < 64; cc++) {
        if (cc < 63) { CP_WAIT1(); } else { CP_WAIT0(); }
        __syncthreads();

        if (cc < 62) {
            const int k0 = (cc + 2) * 16;
            int st = p + 2; if (st >= 3) st -= 3;
            cp16(dA0 + st * STA, srcA0 + k0);
            cp16(dA1 + st * STA, srcA1 + k0);
            cp16(dB0 + st * STB, srcB + (size_t)k0 * ldb);
            cp16(dB0 + st * STB + 16, srcB + (size_t)k0 * ldb + 4);
            CP_COMMIT();
        }

        #pragma unroll
        for (int ks = 0; ks < 2; ks++) {
            const int kk = ks * 8;
            unsigned af[2][4], bf[8][2];
            #pragma unroll
            for (int mt = 0; mt < 2; mt++) {
                int r = warpM + mt * 16 + g;
                af[mt][0] = As[p][r][kk + t4];
                af[mt][1] = As[p][r + 8][kk + t4];
                af[mt][2] = As[p][r][kk + t4 + 4];
                af[mt][3] = As[p][r + 8][kk + t4 + 4];
            }
            #pragma unroll
            for (int nt = 0; nt < 8; nt++) {
                int ncc = warpN + nt * 8 + g;
                bf[nt][0] = Bs[p][kk + t4][ncc];
                bf[nt][1] = Bs[p][kk + t4 + 4][ncc];
            }
            #pragma unroll
            for (int mt = 0; mt < 2; mt++)
                #pragma unroll
                for (int nt = 0; nt < 8; nt++)
                    mma_tf32(c[mt][nt], af[mt], bf[nt]);
        }
        if (++p == 3) p = 0;
    }

    #pragma unroll
    for (int mt = 0; mt < 2; mt++) {
        int r0 = rowBase + warpM + mt * 16 + g;
        int r1 = r0 + 8;
        #pragma unroll
        for (int nt = 0; nt < 8; nt++) {
            int ncc = colBase + warpN + nt * 8 + t4 * 2;
            float bx = bias[ncc], by = bias[ncc + 1];
            float2 w0 = make_float2(c[mt][nt][0] + bx, c[mt][nt][1] + by);
            float2 w1 = make_float2(c[mt][nt][2] + bx, c[mt][nt][3] + by);
            if (rndOut) {
                w0.x = __uint_as_float(f2tf(w0.x));
                w0.y = __uint_as_float(f2tf(w0.y));
                w1.x = __uint_as_float(f2tf(w1.x));
                w1.y = __uint_as_float(f2tf(w1.y));
            }
            *(float2*)(C + (size_t)r0 * D_ + ncc) = w0;
            *(float2*)(C + (size_t)r1 * D_ + ncc) = w1;
        }
    }
}

// ============================================================================
// Flash attention over COMPACTED (unmasked) queries x keys.
// grid = (16 qtiles, B_*H_); blocks beyond ceil(cnt/64) exit.
// Masked keys contribute exactly 0 in the reference (exp underflow), so
// restricting to the compacted list is exact. Pad rows/keys handled via NEG.
// ============================================================================
struct ASmem2 {
    unsigned Qs[64][132];
    unsigned Ks[2][64][132];
    unsigned Vs[2][64][132];
    float    Ps[64][68];
    float    row_max[64];
    float    row_sum[64];
    float    alpha[64];
};

__global__ void __launch_bounds__(256) attn_kernel()
{
    extern __shared__ char smem_raw[];
    ASmem2& s = *reinterpret_cast<ASmem2*>(smem_raw);

    const int bh = blockIdx.y;
    const int b  = bh >> 3;
    const int h  = bh & 7;
    const int cnt = g_cnt[b];
    const int rowBase = blockIdx.x * 64;
    if (rowBase >= cnt) return;
    const int nch = (cnt + 63) >> 6;
    const int* idx = g_idx + b * N_;

    const int tid  = threadIdx.x;
    const int w    = tid >> 5;
    const int lane = tid & 31;
    const int g    = lane >> 2;
    const int t4   = lane & 3;
    const int warpMs = (w & 3) * 16;
    const int warpNs = (w >> 2) * 32;
    const int warpNp = (w >> 2) * 64;

    const float* Qb = g_q + (size_t)b * N_ * D_ + h * HD_;
    const float* Kb = g_k + (size_t)b * N_ * D_ + h * HD_;
    const float* Vb = g_v + (size_t)b * N_ * D_ + h * HD_;

    const int lrow = tid >> 2;          // 0..63
    const int lcol = (tid & 3) * 4;     // +16*i

    const uint32_t ksB = smem_u32(&s.Ks[0][0][0]);
    const uint32_t vsB = smem_u32(&s.Vs[0][0][0]);
    const uint32_t STG_ = 64 * 132 * 4;

    // gather Q tile (tf32 bits already)
    {
        const int qg = (rowBase + lrow < cnt) ? idx[rowBase + lrow] : idx[0];
        #pragma unroll
        for (int i = 0; i < 8; i++) {
            int cc = lcol + 16 * i;
            float4 v = *(const float4*)(Qb + (size_t)qg * D_ + cc);
            s.Qs[lrow][cc + 0] = __float_as_uint(v.x);
            s.Qs[lrow][cc + 1] = __float_as_uint(v.y);
            s.Qs[lrow][cc + 2] = __float_as_uint(v.z);
            s.Qs[lrow][cc + 3] = __float_as_uint(v.w);
        }
    }
    if (tid < 64) {
        s.row_max[tid] = -3.0e38f;
        s.row_sum[tid] = 0.0f;
    }

    float o[8][4];
    #pragma unroll
    for (int nt = 0; nt < 8; nt++)
        #pragma unroll
        for (int i = 0; i < 4; i++) o[nt][i] = 0.0f;

    const int r0 = warpMs + g;
    const int r1 = r0 + 8;

    // prologue: key chunk 0 -> stage 0 (gathered)
    {
        const int kg = (lrow < cnt) ? idx[lrow] : idx[0];
        #pragma unroll
        for (int i = 0; i < 8; i++) {
            int cc = lcol + 16 * i;
            uint32_t off = ((uint32_t)lrow * 132 + cc) * 4;
            cp16(ksB + off, Kb + (size_t)kg * D_ + cc);
            cp16(vsB + off, Vb + (size_t)kg * D_ + cc);
        }
        CP_COMMIT();
    }

    for (int c = 0; c < nch; c++) {
        const int p = c & 1;
        CP_WAIT0();
        __syncthreads();

        if (c + 1 < nch) {
            const int kb = (c + 1) * 64;
            const uint32_t pn = (c + 1) & 1;
            const int kg = (kb + lrow < cnt) ? idx[kb + lrow] : idx[0];
            #pragma unroll
            for (int i = 0; i < 8; i++) {
                int cc = lcol + 16 * i;
                uint32_t off = pn * STG_ + ((uint32_t)lrow * 132 + cc) * 4;
                cp16(ksB + off, Kb + (size_t)kg * D_ + cc);
                cp16(vsB + off, Vb + (size_t)kg * D_ + cc);
            }
            CP_COMMIT();
        }

        // ---- S = Q @ K^T ----
        float sf[4][4];
        #pragma unroll
        for (int nt = 0; nt < 4; nt++)
            #pragma unroll
            for (int i = 0; i < 4; i++) sf[nt][i] = 0.0f;

        #pragma unroll
        for (int kk = 0; kk < 128; kk += 8) {
            unsigned af[4];
            af[0] = s.Qs[r0][kk + t4];
            af[1] = s.Qs[r1][kk + t4];
            af[2] = s.Qs[r0][kk + t4 + 4];
            af[3] = s.Qs[r1][kk + t4 + 4];
            #pragma unroll
            for (int nt = 0; nt < 4; nt++) {
                int kcol = warpNs + nt * 8 + g;
                unsigned bf[2];
                bf[0] = s.Ks[p][kcol][kk + t4];
                bf[1] = s.Ks[p][kcol][kk + t4 + 4];
                mma_tf32(sf[nt], af, bf);
            }
        }
        #pragma unroll
        for (int nt = 0; nt < 4; nt++) {
            int cb = warpNs + nt * 8 + t4 * 2;
            s.Ps[r0][cb]     = sf[nt][0];
            s.Ps[r0][cb + 1] = sf[nt][1];
            s.Ps[r1][cb]     = sf[nt][2];
            s.Ps[r1][cb + 1] = sf[nt][3];
        }
        __syncthreads();

        // ---- quartet softmax: 4 threads/row; pad keys -> NEG ----
        {
            const int r  = tid >> 2;
            const int cb = (tid & 3) * 16;
            const int kbase = c * 64 + cb;
            float m = s.row_max[r];
            float tv[16];
            float cm = -3.0e38f;
            #pragma unroll
            for (int c2 = 0; c2 < 16; c2++) {
                float v = (kbase + c2 < cnt) ? s.Ps[r][cb + c2] * SCALE_ : NEG_;
                tv[c2] = v;
                cm = fmaxf(cm, v);
            }
            cm = fmaxf(cm, __shfl_xor_sync(0xFFFFFFFFu, cm, 1));
            cm = fmaxf(cm, __shfl_xor_sync(0xFFFFFFFFu, cm, 2));
            float nm = fmaxf(m, cm);
            float al = __expf(m - nm);
            float sum = 0.0f;
            #pragma unroll
            for (int c2 = 0; c2 < 16; c2++) {
                float pp = __expf(tv[c2] - nm);
                s.Ps[r][cb + c2] = pp;
                sum += pp;
            }
            sum += __shfl_xor_sync(0xFFFFFFFFu, sum, 1);
            sum += __shfl_xor_sync(0xFFFFFFFFu, sum, 2);
            if ((tid & 3) == 0) {
                s.row_sum[r] = s.row_sum[r] * al + sum;
                s.row_max[r] = nm;
                s.alpha[r]   = al;
            }
        }
        __syncthreads();

        // ---- O = O*alpha + P @ V ----
        float al0 = s.alpha[r0], al1 = s.alpha[r1];
        #pragma unroll
        for (int nt = 0; nt < 8; nt++) {
            o[nt][0] *= al0; o[nt][1] *= al0;
            o[nt][2] *= al1; o[nt][3] *= al1;
        }
        #pragma unroll
        for (int kk = 0; kk < 64; kk += 8) {
            unsigned af[4];
            af[0] = f2tf(s.Ps[r0][kk + t4]);
            af[1] = f2tf(s.Ps[r1][kk + t4]);
            af[2] = f2tf(s.Ps[r0][kk + t4 + 4]);
            af[3] = f2tf(s.Ps[r1][kk + t4 + 4]);
            #pragma unroll
            for (int nt = 0; nt < 8; nt++) {
                int ec = warpNp + nt * 8 + g;
                unsigned bf[2];
                bf[0] = s.Vs[p][kk + t4][ec];
                bf[1] = s.Vs[p][kk + t4 + 4][ec];
                mma_tf32(o[nt], af, bf);
            }
        }
    }

    // ---- epilogue: scatter to original rows ----
    float inv0 = 1.0f / s.row_sum[r0];
    float inv1 = 1.0f / s.row_sum[r1];
    if (rowBase + r0 < cnt) {
        size_t gr = (size_t)(b * N_ + idx[rowBase + r0]) * D_;
        #pragma unroll
        for (int nt = 0; nt < 8; nt++) {
            int cc = h * HD_ + warpNp + nt * 8 + t4 * 2;
            float2 w0;
            w0.x = __uint_as_float(f2tf(o[nt][0] * inv0));
            w0.y = __uint_as_float(f2tf(o[nt][1] * inv0));
            *(float2*)(g_att + gr + cc) = w0;
        }
    }
    if (rowBase + r1 < cnt) {
        size_t gr = (size_t)(b * N_ + idx[rowBase + r1]) * D_;
        #pragma unroll
        for (int nt = 0; nt < 8; nt++) {
            int cc = h * HD_ + warpNp + nt * 8 + t4 * 2;
            float2 w1;
            w1.x = __uint_as_float(f2tf(o[nt][2] * inv1));
            w1.y = __uint_as_float(f2tf(o[nt][3] * inv1));
            *(float2*)(g_att + gr + cc) = w1;
        }
    }
}

// ============================================================================
extern "C" void kernel_launch(void* const* d_in, const int* in_sizes, int n_in,
                              void* d_out, int out_size)
{
    const float* x    = (const float*)d_in[0];
    const int*   xm   = (const int*)d_in[1];
    const float* Wq   = (const float*)d_in[2];
    const float* bq   = (const float*)d_in[3];
    const float* Wk   = (const float*)d_in[4];
    const float* bk   = (const float*)d_in[5];
    const float* Wv   = (const float*)d_in[6];
    const float* bv   = (const float*)d_in[7];
    const float* Wfc  = (const float*)d_in[8];
    const float* bfc  = (const float*)d_in[9];
    float* out = (float*)d_out;

    float *qp, *kp, *vp, *ap, *xp, *wqp, *wkp, *wvp, *wfp;
    cudaGetSymbolAddress((void**)&qp,  g_q);
    cudaGetSymbolAddress((void**)&kp,  g_k);
    cudaGetSymbolAddress((void**)&vp,  g_v);
    cudaGetSymbolAddress((void**)&ap,  g_att);
    cudaGetSymbolAddress((void**)&xp,  g_x);
    cudaGetSymbolAddress((void**)&wqp, g_wq);
    cudaGetSymbolAddress((void**)&wkp, g_wk);
    cudaGetSymbolAddress((void**)&wvp, g_wv);
    cudaGetSymbolAddress((void**)&wfp, g_wf);

    cudaFuncSetAttribute(attn_kernel,
                         cudaFuncAttributeMaxDynamicSharedMemorySize,
                         (int)sizeof(ASmem2));

    // mask compaction (independent of everything else)
    scan_kernel<<<B_, N_>>>(xm);

    // operand pre-conversion to tf32
    const int XN4 = (M_TOT * D_) / 4;
    const int WN4 = (H_ * D_ * HD_) / 4;
    conv_tf32_kernel<<<(XN4 + 255) / 256, 256>>>((const float4*)x,  (float4*)xp,  XN4);
    conv_tf32_kernel<<<(WN4 + 255) / 256, 256>>>((const float4*)Wq, (float4*)wqp, WN4);
    conv_tf32_kernel<<<(WN4 + 255) / 256, 256>>>((const float4*)Wk, (float4*)wkp, WN4);
    conv_tf32_kernel<<<(WN4 + 255) / 256, 256>>>((const float4*)Wv, (float4*)wvp, WN4);
    conv_tf32_kernel<<<(WN4 + 255) / 256, 256>>>((const float4*)Wfc,(float4*)wfp, WN4);

    dim3 gGrid(8, 128);
    gemm_tf32_kernel<<<gGrid, 256>>>(xp, wqp, bq, qp, 1, 1);
    gemm_tf32_kernel<<<gGrid, 256>>>(xp, wkp, bk, kp, 1, 1);
    gemm_tf32_kernel<<<gGrid, 256>>>(xp, wvp, bv, vp, 1, 1);

    // uniform-row result for masked queries
    vmean_kernel<<<dim3(H_, B_), HD_>>>();
    fill_kernel<<<M_TOT, 128>>>(xm);

    // compacted attention
    attn_kernel<<<dim3(16, B_ * H_), 256, sizeof(ASmem2)>>>();

    gemm_tf32_kernel<<<gGrid, 256>>>(ap, wfp, bfc, out, 0, 0);
}

// round 15
// speedup vs baseline: 2.8119x; 1.1861x over previous
#include <cuda_runtime.h>
#include <cstdint>
#include <math.h>

#define B_   16
#define N_   1024
#define D_   1024
#define H_   8
#define HD_  128
#define M_TOT (B_*N_)               /* 16384 */
#define SCALE_ 0.08838834764831845f /* 1/sqrt(128) */
#define NEG_   (-1.0e30f)

// -------- scratch (device globals; allocation is forbidden) --------
__device__ float g_q[(size_t)M_TOT * D_];     // COMPACTED rows, tf32
__device__ float g_k[(size_t)M_TOT * D_];     // COMPACTED rows, tf32
__device__ float g_v[(size_t)M_TOT * D_];     // full rows, tf32
__device__ float g_att[(size_t)M_TOT * D_];   // COMPACTED rows, tf32
__device__ float g_x[(size_t)M_TOT * D_];     // tf32 copy of x
__device__ float g_wq[(size_t)H_ * D_ * HD_];
__device__ float g_wk[(size_t)H_ * D_ * HD_];
__device__ float g_wv[(size_t)H_ * D_ * HD_];
__device__ float g_wf[(size_t)D_ * D_];
__device__ int   g_idx[B_ * N_];              // per-batch compacted indices
__device__ int   g_cnt[B_];                   // per-batch unmasked count
__device__ int   g_off[B_];                   // per-batch slot offset
__device__ int   g_total;                     // total unmasked rows
__device__ int   g_gidx[M_TOT];               // slot -> global row (b*N+n)
__device__ float g_vmean[B_ * D_];            // per-batch mean of v rows
__device__ float g_outm[B_ * D_];             // FC result for masked rows

// -------- helpers --------
__device__ __forceinline__ unsigned f2tf(float x) {
    unsigned r; asm("cvt.rna.tf32.f32 %0, %1;" : "=r"(r) : "f"(x)); return r;
}
__device__ __forceinline__ void mma_tf32(float* d, const unsigned* a, const unsigned* b) {
    asm volatile("mma.sync.aligned.m16n8k8.row.col.f32.tf32.tf32.f32 "
        "{%0,%1,%2,%3},{%4,%5,%6,%7},{%8,%9},{%0,%1,%2,%3};"
        : "+f"(d[0]), "+f"(d[1]), "+f"(d[2]), "+f"(d[3])
        : "r"(a[0]), "r"(a[1]), "r"(a[2]), "r"(a[3]), "r"(b[0]), "r"(b[1]));
}
__device__ __forceinline__ uint32_t smem_u32(const void* p) {
    uint32_t a;
    asm("{ .reg .u64 t; cvta.to.shared.u64 t, %1; cvt.u32.u64 %0, t; }" : "=r"(a) : "l"(p));
    return a;
}
__device__ __forceinline__ void cp16(uint32_t dst, const void* src) {
    asm volatile("cp.async.cg.shared.global [%0], [%1], 16;" :: "r"(dst), "l"(src));
}
#define CP_COMMIT() asm volatile("cp.async.commit_group;" ::: "memory")
#define CP_WAIT0()  asm volatile("cp.async.wait_group 0;" ::: "memory")
#define CP_WAIT1()  asm volatile("cp.async.wait_group 1;" ::: "memory")

// ============================================================================
__global__ void conv_tf32_kernel(const float4* __restrict__ in,
                                 float4* __restrict__ out, int n4)
{
    int i = blockIdx.x * blockDim.x + threadIdx.x;
    if (i < n4) {
        float4 v = in[i];
        float4 w;
        w.x = __uint_as_float(f2tf(v.x));
        w.y = __uint_as_float(f2tf(v.y));
        w.z = __uint_as_float(f2tf(v.z));
        w.w = __uint_as_float(f2tf(v.w));
        out[i] = w;
    }
}

// ============================================================================
// Per-batch prefix scan of mask -> per-batch idx list + count.
// ============================================================================
__global__ void scan_kernel(const int* __restrict__ mask)
{
    __shared__ int sb[N_];
    const int b = blockIdx.x;
    const int t = threadIdx.x;
    const int m = mask[b * N_ + t];
    sb[t] = m;
    __syncthreads();
    #pragma unroll
    for (int off = 1; off < N_; off <<= 1) {
        int v = (t >= off) ? sb[t - off] : 0;
        __syncthreads();
        sb[t] += v;
        __syncthreads();
    }
    if (m) g_idx[b * N_ + sb[t] - 1] = t;
    if (t == N_ - 1) g_cnt[b] = sb[t];
}

// Cross-batch offsets + total (1 block).
__global__ void offset_kernel()
{
    if (threadIdx.x == 0) {
        int acc = 0;
        for (int b = 0; b < B_; b++) { g_off[b] = acc; acc += g_cnt[b]; }
        g_total = acc;
    }
}

// Build global slot -> row map.
__global__ void gidx_kernel()
{
    const int b = blockIdx.x;
    const int off = g_off[b], cnt = g_cnt[b];
    for (int j = threadIdx.x; j < cnt; j += blockDim.x)
        g_gidx[off + j] = b * N_ + g_idx[b * N_ + j];
}

// ============================================================================
// vmean[b][d] = (1/N) * sum_n v[b][n][d]  (tf32-rounded)  grid=(8,B_) blk=128
// ============================================================================
__global__ void vmean_kernel()
{
    const int b = blockIdx.y;
    const int d = blockIdx.x * 128 + threadIdx.x;
    const float* src = g_v + (size_t)b * N_ * D_ + d;
    float acc = 0.0f;
    for (int n = 0; n < N_; n++) acc += src[(size_t)n * D_];
    g_vmean[b * D_ + d] = __uint_as_float(f2tf(acc * (1.0f / N_)));
}

// ============================================================================
// outm[b] = vmean[b] @ Wfc + bfc  (fp32 dot of tf32 operands)
// grid=(8, B_), block=128.
// ============================================================================
__global__ void outm_kernel(const float* __restrict__ bfc)
{
    const int b = blockIdx.y;
    const int col = blockIdx.x * 128 + threadIdx.x;
    const float* vm = g_vmean + b * D_;
    float acc = 0.0f;
    for (int k = 0; k < D_; k++)
        acc += vm[k] * g_wf[(size_t)k * D_ + col];
    g_outm[b * D_ + col] = acc + bfc[col];
}

// Broadcast outm into masked output rows. grid=M_TOT, block=128.
__global__ void fillout_kernel(const int* __restrict__ mask, float* __restrict__ out)
{
    const int row = blockIdx.x;
    if (mask[row]) return;
    const int b = row >> 10;
    float* dst = out + (size_t)row * D_;
    const float* src = g_outm + b * D_;
    for (int d = threadIdx.x; d < D_; d += 128)
        dst[d] = src[d];
}

// ============================================================================
// tf32 GEMM, 3-stage cp.async, optional row gather (A) / scatter (C).
// gatherA: A row = g_gidx[slot]; C row = slot (dense compacted).
// scatterC: A row = slot (dense compacted); C row = g_gidx[slot], predicated.
// Early-exit on slot tiles beyond g_total when gatherA|scatterC.
// ============================================================================
__global__ void __launch_bounds__(256, 2) gemm_tf32_kernel(
    const float* __restrict__ A,
    const float* __restrict__ Bsrc,
    const float* __restrict__ bias,
    float* __restrict__ C,
    int headMode, int rndOut, int gatherA, int scatterC)
{
    __shared__ unsigned As[3][128][20];
    __shared__ unsigned Bs[3][16][136];

    const int rowBase = blockIdx.y * 128;
    const int colTile = blockIdx.x;
    const int colBase = colTile * 128;

    const int total = (gatherA | scatterC) ? g_total : M_TOT;
    if (rowBase >= total) return;

    const float* Bp;
    int ldb;
    if (headMode) { Bp = Bsrc + (size_t)colTile * D_ * HD_; ldb = HD_; }
    else          { Bp = Bsrc + colBase;                    ldb = D_;  }

    const int tid  = threadIdx.x;
    const int w    = tid >> 5;
    const int lane = tid & 31;
    const int g    = lane >> 2;
    const int t4   = lane & 3;
    const int warpM = (w & 3) * 32;
    const int warpN = (w >> 2) * 64;

    float c[2][8][4];
    #pragma unroll
    for (int mt = 0; mt < 2; mt++)
        #pragma unroll
        for (int nt = 0; nt < 8; nt++)
            #pragma unroll
            for (int i = 0; i < 4; i++) c[mt][nt][i] = 0.0f;

    const int arow = tid >> 2;
    const int acol = (tid & 3) * 4;
    const int brow = tid >> 4;
    const int bcol = (tid & 15) * 8;

    // resolve A source rows (gather or dense)
    int slot0 = rowBase + arow, slot1 = rowBase + arow + 64;
    int ar0, ar1;
    if (gatherA) {
        ar0 = (slot0 < total) ? g_gidx[slot0] : g_gidx[rowBase];
        ar1 = (slot1 < total) ? g_gidx[slot1] : g_gidx[rowBase];
    } else {
        ar0 = slot0; ar1 = slot1;
    }

    const uint32_t asB = smem_u32(&As[0][0][0]);
    const uint32_t bsB = smem_u32(&Bs[0][0][0]);
    const uint32_t dA0 = asB + ((uint32_t)arow * 20 + acol) * 4;
    const uint32_t dA1 = asB + ((uint32_t)(arow + 64) * 20 + acol) * 4;
    const uint32_t dB0 = bsB + ((uint32_t)brow * 136 + bcol) * 4;
    const uint32_t STA = 128 * 20 * 4;
    const uint32_t STB = 16 * 136 * 4;

    const float* srcA0 = A + (size_t)ar0 * D_ + acol;
    const float* srcA1 = A + (size_t)ar1 * D_ + acol;
    const float* srcB  = Bp + (size_t)brow * ldb + bcol;

    #pragma unroll
    for (int pc = 0; pc < 2; pc++) {
        const int k0 = pc * 16;
        cp16(dA0 + pc * STA, srcA0 + k0);
        cp16(dA1 + pc * STA, srcA1 + k0);
        cp16(dB0 + pc * STB, srcB + (size_t)k0 * ldb);
        cp16(dB0 + pc * STB + 16, srcB + (size_t)k0 * ldb + 4);
        CP_COMMIT();
    }

    int p = 0;
    for (int cc = 0; cc < 64; cc++) {
        if (cc < 63) { CP_WAIT1(); } else { CP_WAIT0(); }
        __syncthreads();

        if (cc < 62) {
            const int k0 = (cc + 2) * 16;
            int st = p + 2; if (st >= 3) st -= 3;
            cp16(dA0 + st * STA, srcA0 + k0);
            cp16(dA1 + st * STA, srcA1 + k0);
            cp16(dB0 + st * STB, srcB + (size_t)k0 * ldb);
            cp16(dB0 + st * STB + 16, srcB + (size_t)k0 * ldb + 4);
            CP_COMMIT();
        }

        #pragma unroll
        for (int ks = 0; ks < 2; ks++) {
            const int kk = ks * 8;
            unsigned af[2][4], bf[8][2];
            #pragma unroll
            for (int mt = 0; mt < 2; mt++) {
                int r = warpM + mt * 16 + g;
                af[mt][0] = As[p][r][kk + t4];
                af[mt][1] = As[p][r + 8][kk + t4];
                af[mt][2] = As[p][r][kk + t4 + 4];
                af[mt][3] = As[p][r + 8][kk + t4 + 4];
            }
            #pragma unroll
            for (int nt = 0; nt < 8; nt++) {
                int ncc = warpN + nt * 8 + g;
                bf[nt][0] = Bs[p][kk + t4][ncc];
                bf[nt][1] = Bs[p][kk + t4 + 4][ncc];
            }
            #pragma unroll
            for (int mt = 0; mt < 2; mt++)
                #pragma unroll
                for (int nt = 0; nt < 8; nt++)
                    mma_tf32(c[mt][nt], af[mt], bf[nt]);
        }
        if (++p == 3) p = 0;
    }

    #pragma unroll
    for (int mt = 0; mt < 2; mt++) {
        int s0 = rowBase + warpM + mt * 16 + g;
        int s1 = s0 + 8;
        int cr0 = s0, cr1 = s1;
        bool st0 = true, st1 = true;
        if (scatterC) {
            st0 = (s0 < total); st1 = (s1 < total);
            if (st0) cr0 = g_gidx[s0];
            if (st1) cr1 = g_gidx[s1];
        }
        #pragma unroll
        for (int nt = 0; nt < 8; nt++) {
            int ncc = colBase + warpN + nt * 8 + t4 * 2;
            float bx = bias[ncc], by = bias[ncc + 1];
            float2 w0 = make_float2(c[mt][nt][0] + bx, c[mt][nt][1] + by);
            float2 w1 = make_float2(c[mt][nt][2] + bx, c[mt][nt][3] + by);
            if (rndOut) {
                w0.x = __uint_as_float(f2tf(w0.x));
                w0.y = __uint_as_float(f2tf(w0.y));
                w1.x = __uint_as_float(f2tf(w1.x));
                w1.y = __uint_as_float(f2tf(w1.y));
            }
            if (st0) *(float2*)(C + (size_t)cr0 * D_ + ncc) = w0;
            if (st1) *(float2*)(C + (size_t)cr1 * D_ + ncc) = w1;
        }
    }
}

// ============================================================================
// Flash attention over compacted rows. q/k read DENSE from compacted slots;
// v gathered from full storage. Output written dense compacted to g_att.
// ============================================================================
struct ASmem2 {
    unsigned Qs[64][132];
    unsigned Ks[2][64][132];
    unsigned Vs[2][64][132];
    float    Ps[64][68];
    float    row_max[64];
    float    row_sum[64];
    float    alpha[64];
};

__global__ void __launch_bounds__(256) attn_kernel()
{
    extern __shared__ char smem_raw[];
    ASmem2& s = *reinterpret_cast<ASmem2*>(smem_raw);

    const int bh = blockIdx.y;
    const int b  = bh >> 3;
    const int h  = bh & 7;
    const int cnt = g_cnt[b];
    const int off = g_off[b];
    const int rowBase = blockIdx.x * 64;
    if (rowBase >= cnt) return;
    const int nch = (cnt + 63) >> 6;
    const int* idx = g_idx + b * N_;

    const int tid  = threadIdx.x;
    const int w    = tid >> 5;
    const int lane = tid & 31;
    const int g    = lane >> 2;
    const int t4   = lane & 3;
    const int warpMs = (w & 3) * 16;
    const int warpNs = (w >> 2) * 32;
    const int warpNp = (w >> 2) * 64;

    const float* Qb = g_q + (size_t)off * D_ + h * HD_;   // dense compacted
    const float* Kb = g_k + (size_t)off * D_ + h * HD_;
    const float* Vb = g_v + (size_t)b * N_ * D_ + h * HD_;

    const int lrow = tid >> 2;          // 0..63
    const int lcol = (tid & 3) * 4;     // +16*i

    const uint32_t ksB = smem_u32(&s.Ks[0][0][0]);
    const uint32_t vsB = smem_u32(&s.Vs[0][0][0]);
    const uint32_t STG_ = 64 * 132 * 4;

    // Q tile: dense
    {
        const int qr = (rowBase + lrow < cnt) ? (rowBase + lrow) : 0;
        #pragma unroll
        for (int i = 0; i < 8; i++) {
            int cc = lcol + 16 * i;
            float4 v = *(const float4*)(Qb + (size_t)qr * D_ + cc);
            s.Qs[lrow][cc + 0] = __float_as_uint(v.x);
            s.Qs[lrow][cc + 1] = __float_as_uint(v.y);
            s.Qs[lrow][cc + 2] = __float_as_uint(v.z);
            s.Qs[lrow][cc + 3] = __float_as_uint(v.w);
        }
    }
    if (tid < 64) {
        s.row_max[tid] = -3.0e38f;
        s.row_sum[tid] = 0.0f;
    }

    float o[8][4];
    #pragma unroll
    for (int nt = 0; nt < 8; nt++)
        #pragma unroll
        for (int i = 0; i < 4; i++) o[nt][i] = 0.0f;

    const int r0 = warpMs + g;
    const int r1 = r0 + 8;

    // prologue: key chunk 0
    {
        const int kr = (lrow < cnt) ? lrow : 0;
        const int vg = (lrow < cnt) ? idx[lrow] : idx[0];
        #pragma unroll
        for (int i = 0; i < 8; i++) {
            int cc = lcol + 16 * i;
            uint32_t offb = ((uint32_t)lrow * 132 + cc) * 4;
            cp16(ksB + offb, Kb + (size_t)kr * D_ + cc);
            cp16(vsB + offb, Vb + (size_t)vg * D_ + cc);
        }
        CP_COMMIT();
    }

    for (int c = 0; c < nch; c++) {
        const int p = c & 1;
        CP_WAIT0();
        __syncthreads();

        if (c + 1 < nch) {
            const int kb = (c + 1) * 64;
            const uint32_t pn = (c + 1) & 1;
            const int kr = (kb + lrow < cnt) ? (kb + lrow) : 0;
            const int vg = (kb + lrow < cnt) ? idx[kb + lrow] : idx[0];
            #pragma unroll
            for (int i = 0; i < 8; i++) {
                int cc = lcol + 16 * i;
                uint32_t offb = pn * STG_ + ((uint32_t)lrow * 132 + cc) * 4;
                cp16(ksB + offb, Kb + (size_t)kr * D_ + cc);
                cp16(vsB + offb, Vb + (size_t)vg * D_ + cc);
            }
            CP_COMMIT();
        }

        // ---- S = Q @ K^T ----
        float sf[4][4];
        #pragma unroll
        for (int nt = 0; nt < 4; nt++)
            #pragma unroll
            for (int i = 0; i < 4; i++) sf[nt][i] = 0.0f;

        #pragma unroll
        for (int kk = 0; kk < 128; kk += 8) {
            unsigned af[4];
            af[0] = s.Qs[r0][kk + t4];
            af[1] = s.Qs[r1][kk + t4];
            af[2] = s.Qs[r0][kk + t4 + 4];
            af[3] = s.Qs[r1][kk + t4 + 4];
            #pragma unroll
            for (int nt = 0; nt < 4; nt++) {
                int kcol = warpNs + nt * 8 + g;
                unsigned bf[2];
                bf[0] = s.Ks[p][kcol][kk + t4];
                bf[1] = s.Ks[p][kcol][kk + t4 + 4];
                mma_tf32(sf[nt], af, bf);
            }
        }
        #pragma unroll
        for (int nt = 0; nt < 4; nt++) {
            int cb = warpNs + nt * 8 + t4 * 2;
            s.Ps[r0][cb]     = sf[nt][0];
            s.Ps[r0][cb + 1] = sf[nt][1];
            s.Ps[r1][cb]     = sf[nt][2];
            s.Ps[r1][cb + 1] = sf[nt][3];
        }
        __syncthreads();

        // ---- quartet softmax ----
        {
            const int r  = tid >> 2;
            const int cb = (tid & 3) * 16;
            const int kbase = c * 64 + cb;
            float m = s.row_max[r];
            float tv[16];
            float cm = -3.0e38f;
            #pragma unroll
            for (int c2 = 0; c2 < 16; c2++) {
                float v = (kbase + c2 < cnt) ? s.Ps[r][cb + c2] * SCALE_ : NEG_;
                tv[c2] = v;
                cm = fmaxf(cm, v);
            }
            cm = fmaxf(cm, __shfl_xor_sync(0xFFFFFFFFu, cm, 1));
            cm = fmaxf(cm, __shfl_xor_sync(0xFFFFFFFFu, cm, 2));
            float nm = fmaxf(m, cm);
            float al = __expf(m - nm);
            float sum = 0.0f;
            #pragma unroll
            for (int c2 = 0; c2 < 16; c2++) {
                float pp = __expf(tv[c2] - nm);
                s.Ps[r][cb + c2] = pp;
                sum += pp;
            }
            sum += __shfl_xor_sync(0xFFFFFFFFu, sum, 1);
            sum += __shfl_xor_sync(0xFFFFFFFFu, sum, 2);
            if ((tid & 3) == 0) {
                s.row_sum[r] = s.row_sum[r] * al + sum;
                s.row_max[r] = nm;
                s.alpha[r]   = al;
            }
        }
        __syncthreads();

        // ---- O = O*alpha + P @ V ----
        float al0 = s.alpha[r0], al1 = s.alpha[r1];
        #pragma unroll
        for (int nt = 0; nt < 8; nt++) {
            o[nt][0] *= al0; o[nt][1] *= al0;
            o[nt][2] *= al1; o[nt][3] *= al1;
        }
        #pragma unroll
        for (int kk = 0; kk < 64; kk += 8) {
            unsigned af[4];
            af[0] = f2tf(s.Ps[r0][kk + t4]);
            af[1] = f2tf(s.Ps[r1][kk + t4]);
            af[2] = f2tf(s.Ps[r0][kk + t4 + 4]);
            af[3] = f2tf(s.Ps[r1][kk + t4 + 4]);
            #pragma unroll
            for (int nt = 0; nt < 8; nt++) {
                int ec = warpNp + nt * 8 + g;
                unsigned bf[2];
                bf[0] = s.Vs[p][kk + t4][ec];
                bf[1] = s.Vs[p][kk + t4 + 4][ec];
                mma_tf32(o[nt], af, bf);
            }
        }
    }

    // ---- epilogue: write dense compacted rows ----
    float inv0 = 1.0f / s.row_sum[r0];
    float inv1 = 1.0f / s.row_sum[r1];
    if (rowBase + r0 < cnt) {
        size_t gr = (size_t)(off + rowBase + r0) * D_;
        #pragma unroll
        for (int nt = 0; nt < 8; nt++) {
            int cc = h * HD_ + warpNp + nt * 8 + t4 * 2;
            float2 w0;
            w0.x = __uint_as_float(f2tf(o[nt][0] * inv0));
            w0.y = __uint_as_float(f2tf(o[nt][1] * inv0));
            *(float2*)(g_att + gr + cc) = w0;
        }
    }
    if (rowBase + r1 < cnt) {
        size_t gr = (size_t)(off + rowBase + r1) * D_;
        #pragma unroll
        for (int nt = 0; nt < 8; nt++) {
            int cc = h * HD_ + warpNp + nt * 8 + t4 * 2;
            float2 w1;
            w1.x = __uint_as_float(f2tf(o[nt][2] * inv1));
            w1.y = __uint_as_float(f2tf(o[nt][3] * inv1));
            *(float2*)(g_att + gr + cc) = w1;
        }
    }
}

// ============================================================================
extern "C" void kernel_launch(void* const* d_in, const int* in_sizes, int n_in,
                              void* d_out, int out_size)
{
    const float* x    = (const float*)d_in[0];
    const int*   xm   = (const int*)d_in[1];
    const float* Wq   = (const float*)d_in[2];
    const float* bq   = (const float*)d_in[3];
    const float* Wk   = (const float*)d_in[4];
    const float* bk   = (const float*)d_in[5];
    const float* Wv   = (const float*)d_in[6];
    const float* bv   = (const float*)d_in[7];
    const float* Wfc  = (const float*)d_in[8];
    const float* bfc  = (const float*)d_in[9];
    float* out = (float*)d_out;

    float *qp, *kp, *vp, *ap, *xp, *wqp, *wkp, *wvp, *wfp;
    cudaGetSymbolAddress((void**)&qp,  g_q);
    cudaGetSymbolAddress((void**)&kp,  g_k);
    cudaGetSymbolAddress((void**)&vp,  g_v);
    cudaGetSymbolAddress((void**)&ap,  g_att);
    cudaGetSymbolAddress((void**)&xp,  g_x);
    cudaGetSymbolAddress((void**)&wqp, g_wq);
    cudaGetSymbolAddress((void**)&wkp, g_wk);
    cudaGetSymbolAddress((void**)&wvp, g_wv);
    cudaGetSymbolAddress((void**)&wfp, g_wf);

    cudaFuncSetAttribute(attn_kernel,
                         cudaFuncAttributeMaxDynamicSharedMemorySize,
                         (int)sizeof(ASmem2));

    // mask compaction
    scan_kernel<<<B_, N_>>>(xm);
    offset_kernel<<<1, 32>>>();
    gidx_kernel<<<B_, 256>>>();

    // operand pre-conversion to tf32
    const int XN4 = (M_TOT * D_) / 4;
    const int WN4 = (H_ * D_ * HD_) / 4;
    conv_tf32_kernel<<<(XN4 + 255) / 256, 256>>>((const float4*)x,  (float4*)xp,  XN4);
    conv_tf32_kernel<<<(WN4 + 255) / 256, 256>>>((const float4*)Wq, (float4*)wqp, WN4);
    conv_tf32_kernel<<<(WN4 + 255) / 256, 256>>>((const float4*)Wk, (float4*)wkp, WN4);
    conv_tf32_kernel<<<(WN4 + 255) / 256, 256>>>((const float4*)Wv, (float4*)wvp, WN4);
    conv_tf32_kernel<<<(WN4 + 255) / 256, 256>>>((const float4*)Wfc,(float4*)wfp, WN4);

    dim3 gGrid(8, 128);
    // Q, K: gather-A, dense compacted C (only ~total rows computed)
    gemm_tf32_kernel<<<gGrid, 256>>>(xp, wqp, bq, qp, 1, 1, 1, 0);
    gemm_tf32_kernel<<<gGrid, 256>>>(xp, wkp, bk, kp, 1, 1, 1, 0);
    // V: full dense (vmean needs all rows)
    gemm_tf32_kernel<<<gGrid, 256>>>(xp, wvp, bv, vp, 1, 1, 0, 0);

    // masked-row path: vmean -> outm (fp32 dot), broadcast later
    vmean_kernel<<<dim3(8, B_), 128>>>();
    outm_kernel<<<dim3(8, B_), 128>>>(bfc);
    fillout_kernel<<<M_TOT, 128>>>(xm, out);

    // compacted attention
    attn_kernel<<<dim3(16, B_ * H_), 256, sizeof(ASmem2)>>>();

    // FC: dense compacted A, scattered C (only ~total rows computed)
    gemm_tf32_kernel<<<gGrid, 256>>>(ap, wfp, bfc, out, 0, 0, 0, 1);
}

// round 16
// speedup vs baseline: 3.0702x; 1.0918x over previous
#include <cuda_runtime.h>
#include <cstdint>
#include <math.h>

#define B_   16
#define N_   1024
#define D_   1024
#define H_   8
#define HD_  128
#define M_TOT (B_*N_)               /* 16384 */
#define SCALE_ 0.08838834764831845f /* 1/sqrt(128) */
#define NEG_   (-1.0e30f)

// -------- scratch (device globals; allocation is forbidden) --------
__device__ float g_q[(size_t)M_TOT * D_];     // COMPACTED rows, tf32
__device__ float g_k[(size_t)M_TOT * D_];     // COMPACTED rows, tf32
__device__ float g_v[(size_t)M_TOT * D_];     // COMPACTED rows, tf32
__device__ float g_att[(size_t)M_TOT * D_];   // COMPACTED rows, tf32
__device__ float g_x[(size_t)M_TOT * D_];     // tf32 copy of x
__device__ float g_wq[(size_t)H_ * D_ * HD_];
__device__ float g_wk[(size_t)H_ * D_ * HD_];
__device__ float g_wv[(size_t)H_ * D_ * HD_];
__device__ float g_wf[(size_t)D_ * D_];
__device__ int   g_idx[B_ * N_];              // per-batch compacted indices
__device__ int   g_cnt[B_];                   // per-batch unmasked count
__device__ int   g_off[B_];                   // per-batch slot offset
__device__ int   g_total;                     // total unmasked rows
__device__ int   g_gidx[M_TOT];               // slot -> global row (b*N+n)
__device__ float g_xmean[B_ * D_];            // per-batch mean of x rows (fp32)
__device__ float g_vmean[B_ * D_];            // = xmean @ Wv + bv  (tf32)
__device__ float g_outm[B_ * D_];             // FC result for masked rows

// -------- helpers --------
__device__ __forceinline__ unsigned f2tf(float x) {
    unsigned r; asm("cvt.rna.tf32.f32 %0, %1;" : "=r"(r) : "f"(x)); return r;
}
__device__ __forceinline__ void mma_tf32(float* d, const unsigned* a, const unsigned* b) {
    asm volatile("mma.sync.aligned.m16n8k8.row.col.f32.tf32.tf32.f32 "
        "{%0,%1,%2,%3},{%4,%5,%6,%7},{%8,%9},{%0,%1,%2,%3};"
        : "+f"(d[0]), "+f"(d[1]), "+f"(d[2]), "+f"(d[3])
        : "r"(a[0]), "r"(a[1]), "r"(a[2]), "r"(a[3]), "r"(b[0]), "r"(b[1]));
}
__device__ __forceinline__ uint32_t smem_u32(const void* p) {
    uint32_t a;
    asm("{ .reg .u64 t; cvta.to.shared.u64 t, %1; cvt.u32.u64 %0, t; }" : "=r"(a) : "l"(p));
    return a;
}
__device__ __forceinline__ void cp16(uint32_t dst, const void* src) {
    asm volatile("cp.async.cg.shared.global [%0], [%1], 16;" :: "r"(dst), "l"(src));
}
#define CP_COMMIT() asm volatile("cp.async.commit_group;" ::: "memory")
#define CP_WAIT0()  asm volatile("cp.async.wait_group 0;" ::: "memory")
#define CP_WAIT1()  asm volatile("cp.async.wait_group 1;" ::: "memory")

// ============================================================================
__global__ void conv_tf32_kernel(const float4* __restrict__ in,
                                 float4* __restrict__ out, int n4)
{
    int i = blockIdx.x * blockDim.x + threadIdx.x;
    if (i < n4) {
        float4 v = in[i];
        float4 w;
        w.x = __uint_as_float(f2tf(v.x));
        w.y = __uint_as_float(f2tf(v.y));
        w.z = __uint_as_float(f2tf(v.z));
        w.w = __uint_as_float(f2tf(v.w));
        out[i] = w;
    }
}

// ============================================================================
// Per-batch prefix scan of mask -> per-batch idx list + count.
// ============================================================================
__global__ void scan_kernel(const int* __restrict__ mask)
{
    __shared__ int sb[N_];
    const int b = blockIdx.x;
    const int t = threadIdx.x;
    const int m = mask[b * N_ + t];
    sb[t] = m;
    __syncthreads();
    #pragma unroll
    for (int off = 1; off < N_; off <<= 1) {
        int v = (t >= off) ? sb[t - off] : 0;
        __syncthreads();
        sb[t] += v;
        __syncthreads();
    }
    if (m) g_idx[b * N_ + sb[t] - 1] = t;
    if (t == N_ - 1) g_cnt[b] = sb[t];
}

__global__ void offset_kernel()
{
    if (threadIdx.x == 0) {
        int acc = 0;
        for (int b = 0; b < B_; b++) { g_off[b] = acc; acc += g_cnt[b]; }
        g_total = acc;
    }
}

__global__ void gidx_kernel()
{
    const int b = blockIdx.x;
    const int off = g_off[b], cnt = g_cnt[b];
    for (int j = threadIdx.x; j < cnt; j += blockDim.x)
        g_gidx[off + j] = b * N_ + g_idx[b * N_ + j];
}

// ============================================================================
// xmean[b][d] = (1/N) * sum_n x[b][n][d]   grid=(8,B_) blk=128, fp32.
// ============================================================================
__global__ void xmean_kernel()
{
    const int b = blockIdx.y;
    const int d = blockIdx.x * 128 + threadIdx.x;
    const float* src = g_x + (size_t)b * N_ * D_ + d;
    float acc = 0.0f;
    for (int n = 0; n < N_; n++) acc += src[(size_t)n * D_];
    g_xmean[b * D_ + d] = acc * (1.0f / N_);
}

// ============================================================================
// vmean[b][h*HD+e] = xmean[b] . Wv[h][:,e] + bv  (linearity: == mean of v rows)
// grid=(H_, B_), blk=128.
// ============================================================================
__global__ void vmeanlin_kernel(const float* __restrict__ bv)
{
    const int h = blockIdx.x, b = blockIdx.y, e = threadIdx.x;
    const float* xm = g_xmean + b * D_;
    const float* wv = g_wv + (size_t)h * D_ * HD_ + e;
    float acc = 0.0f;
    for (int d = 0; d < D_; d++) acc += xm[d] * wv[(size_t)d * HD_];
    g_vmean[b * D_ + h * HD_ + e] =
        __uint_as_float(f2tf(acc + bv[h * HD_ + e]));
}

// ============================================================================
// outm[b] = vmean[b] @ Wfc + bfc   grid=(8, B_), blk=128.
// ============================================================================
__global__ void outm_kernel(const float* __restrict__ bfc)
{
    const int b = blockIdx.y;
    const int col = blockIdx.x * 128 + threadIdx.x;
    const float* vm = g_vmean + b * D_;
    float acc = 0.0f;
    for (int k = 0; k < D_; k++)
        acc += vm[k] * g_wf[(size_t)k * D_ + col];
    g_outm[b * D_ + col] = acc + bfc[col];
}

// Broadcast outm into masked output rows. grid=M_TOT, block=128.
__global__ void fillout_kernel(const int* __restrict__ mask, float* __restrict__ out)
{
    const int row = blockIdx.x;
    if (mask[row]) return;
    const int b = row >> 10;
    float* dst = out + (size_t)row * D_;
    const float* src = g_outm + b * D_;
    for (int d = threadIdx.x; d < D_; d += 128)
        dst[d] = src[d];
}

// ============================================================================
// Fused QKV GEMM: grid.x = 24 (sel = x/8 in {Q,K,V}, head = x&7), grid.y slots.
// A rows gathered via g_gidx; C rows dense compacted; output tf32-rounded.
// 3-stage cp.async pipeline, block tile 128x128, BK=16, 256 threads.
// ============================================================================
__global__ void __launch_bounds__(256, 2) qkv_gemm_kernel(
    const float* __restrict__ A,
    const float* __restrict__ wq, const float* __restrict__ wk,
    const float* __restrict__ wv,
    const float* __restrict__ bq, const float* __restrict__ bk,
    const float* __restrict__ bv)
{
    __shared__ unsigned As[3][128][20];
    __shared__ unsigned Bs[3][16][136];

    const int rowBase = blockIdx.y * 128;
    const int total = g_total;
    if (rowBase >= total) return;

    const int colTile = blockIdx.x;
    const int sel = colTile >> 3;
    const int h   = colTile & 7;
    const int colBase = h * 128;

    const float* Bp   = (sel == 0 ? wq : sel == 1 ? wk : wv) + (size_t)h * D_ * HD_;
    const float* bias = (sel == 0 ? bq : sel == 1 ? bk : bv);
    float* C          = (sel == 0 ? g_q : sel == 1 ? g_k : g_v);
    const int ldb = HD_;

    const int tid  = threadIdx.x;
    const int w    = tid >> 5;
    const int lane = tid & 31;
    const int g    = lane >> 2;
    const int t4   = lane & 3;
    const int warpM = (w & 3) * 32;
    const int warpN = (w >> 2) * 64;

    float c[2][8][4];
    #pragma unroll
    for (int mt = 0; mt < 2; mt++)
        #pragma unroll
        for (int nt = 0; nt < 8; nt++)
            #pragma unroll
            for (int i = 0; i < 4; i++) c[mt][nt][i] = 0.0f;

    const int arow = tid >> 2;
    const int acol = (tid & 3) * 4;
    const int brow = tid >> 4;
    const int bcol = (tid & 15) * 8;

    const int slot0 = rowBase + arow, slot1 = rowBase + arow + 64;
    const int ar0 = (slot0 < total) ? g_gidx[slot0] : g_gidx[rowBase];
    const int ar1 = (slot1 < total) ? g_gidx[slot1] : g_gidx[rowBase];

    const uint32_t asB = smem_u32(&As[0][0][0]);
    const uint32_t bsB = smem_u32(&Bs[0][0][0]);
    const uint32_t dA0 = asB + ((uint32_t)arow * 20 + acol) * 4;
    const uint32_t dA1 = asB + ((uint32_t)(arow + 64) * 20 + acol) * 4;
    const uint32_t dB0 = bsB + ((uint32_t)brow * 136 + bcol) * 4;
    const uint32_t STA = 128 * 20 * 4;
    const uint32_t STB = 16 * 136 * 4;

    const float* srcA0 = A + (size_t)ar0 * D_ + acol;
    const float* srcA1 = A + (size_t)ar1 * D_ + acol;
    const float* srcB  = Bp + (size_t)brow * ldb + bcol;

    #pragma unroll
    for (int pc = 0; pc < 2; pc++) {
        const int k0 = pc * 16;
        cp16(dA0 + pc * STA, srcA0 + k0);
        cp16(dA1 + pc * STA, srcA1 + k0);
        cp16(dB0 + pc * STB, srcB + (size_t)k0 * ldb);
        cp16(dB0 + pc * STB + 16, srcB + (size_t)k0 * ldb + 4);
        CP_COMMIT();
    }

    int p = 0;
    for (int cc = 0; cc < 64; cc++) {
        if (cc < 63) { CP_WAIT1(); } else { CP_WAIT0(); }
        __syncthreads();

        if (cc < 62) {
            const int k0 = (cc + 2) * 16;
            int st = p + 2; if (st >= 3) st -= 3;
            cp16(dA0 + st * STA, srcA0 + k0);
            cp16(dA1 + st * STA, srcA1 + k0);
            cp16(dB0 + st * STB, srcB + (size_t)k0 * ldb);
            cp16(dB0 + st * STB + 16, srcB + (size_t)k0 * ldb + 4);
            CP_COMMIT();
        }

        #pragma unroll
        for (int ks = 0; ks < 2; ks++) {
            const int kk = ks * 8;
            unsigned af[2][4], bf[8][2];
            #pragma unroll
            for (int mt = 0; mt < 2; mt++) {
                int r = warpM + mt * 16 + g;
                af[mt][0] = As[p][r][kk + t4];
                af[mt][1] = As[p][r + 8][kk + t4];
                af[mt][2] = As[p][r][kk + t4 + 4];
                af[mt][3] = As[p][r + 8][kk + t4 + 4];
            }
            #pragma unroll
            for (int nt = 0; nt < 8; nt++) {
                int ncc = warpN + nt * 8 + g;
                bf[nt][0] = Bs[p][kk + t4][ncc];
                bf[nt][1] = Bs[p][kk + t4 + 4][ncc];
            }
            #pragma unroll
            for (int mt = 0; mt < 2; mt++)
                #pragma unroll
                for (int nt = 0; nt < 8; nt++)
                    mma_tf32(c[mt][nt], af[mt], bf[nt]);
        }
        if (++p == 3) p = 0;
    }

    #pragma unroll
    for (int mt = 0; mt < 2; mt++) {
        int s0 = rowBase + warpM + mt * 16 + g;
        int s1 = s0 + 8;
        #pragma unroll
        for (int nt = 0; nt < 8; nt++) {
            int ncc = colBase + warpN + nt * 8 + t4 * 2;
            float bx = bias[ncc], by = bias[ncc + 1];
            float2 w0, w1;
            w0.x = __uint_as_float(f2tf(c[mt][nt][0] + bx));
            w0.y = __uint_as_float(f2tf(c[mt][nt][1] + by));
            w1.x = __uint_as_float(f2tf(c[mt][nt][2] + bx));
            w1.y = __uint_as_float(f2tf(c[mt][nt][3] + by));
            *(float2*)(C + (size_t)s0 * D_ + ncc) = w0;
            *(float2*)(C + (size_t)s1 * D_ + ncc) = w1;
        }
    }
}

// ============================================================================
// FC GEMM: dense compacted A (g_att), scattered C rows via g_gidx.
// ============================================================================
__global__ void __launch_bounds__(256, 2) fc_gemm_kernel(
    const float* __restrict__ A,
    const float* __restrict__ Bsrc,
    const float* __restrict__ bias,
    float* __restrict__ C)
{
    __shared__ unsigned As[3][128][20];
    __shared__ unsigned Bs[3][16][136];

    const int rowBase = blockIdx.y * 128;
    const int total = g_total;
    if (rowBase >= total) return;

    const int colBase = blockIdx.x * 128;
    const float* Bp = Bsrc + colBase;
    const int ldb = D_;

    const int tid  = threadIdx.x;
    const int w    = tid >> 5;
    const int lane = tid & 31;
    const int g    = lane >> 2;
    const int t4   = lane & 3;
    const int warpM = (w & 3) * 32;
    const int warpN = (w >> 2) * 64;

    float c[2][8][4];
    #pragma unroll
    for (int mt = 0; mt < 2; mt++)
        #pragma unroll
        for (int nt = 0; nt < 8; nt++)
            #pragma unroll
            for (int i = 0; i < 4; i++) c[mt][nt][i] = 0.0f;

    const int arow = tid >> 2;
    const int acol = (tid & 3) * 4;
    const int brow = tid >> 4;
    const int bcol = (tid & 15) * 8;

    const uint32_t asB = smem_u32(&As[0][0][0]);
    const uint32_t bsB = smem_u32(&Bs[0][0][0]);
    const uint32_t dA0 = asB + ((uint32_t)arow * 20 + acol) * 4;
    const uint32_t dA1 = asB + ((uint32_t)(arow + 64) * 20 + acol) * 4;
    const uint32_t dB0 = bsB + ((uint32_t)brow * 136 + bcol) * 4;
    const uint32_t STA = 128 * 20 * 4;
    const uint32_t STB = 16 * 136 * 4;

    const float* srcA0 = A + (size_t)(rowBase + arow) * D_ + acol;
    const float* srcA1 = A + (size_t)(rowBase + arow + 64) * D_ + acol;
    const float* srcB  = Bp + (size_t)brow * ldb + bcol;

    #pragma unroll
    for (int pc = 0; pc < 2; pc++) {
        const int k0 = pc * 16;
        cp16(dA0 + pc * STA, srcA0 + k0);
        cp16(dA1 + pc * STA, srcA1 + k0);
        cp16(dB0 + pc * STB, srcB + (size_t)k0 * ldb);
        cp16(dB0 + pc * STB + 16, srcB + (size_t)k0 * ldb + 4);
        CP_COMMIT();
    }

    int p = 0;
    for (int cc = 0; cc < 64; cc++) {
        if (cc < 63) { CP_WAIT1(); } else { CP_WAIT0(); }
        __syncthreads();

        if (cc < 62) {
            const int k0 = (cc + 2) * 16;
            int st = p + 2; if (st >= 3) st -= 3;
            cp16(dA0 + st * STA, srcA0 + k0);
            cp16(dA1 + st * STA, srcA1 + k0);
            cp16(dB0 + st * STB, srcB + (size_t)k0 * ldb);
            cp16(dB0 + st * STB + 16, srcB + (size_t)k0 * ldb + 4);
            CP_COMMIT();
        }

        #pragma unroll
        for (int ks = 0; ks < 2; ks++) {
            const int kk = ks * 8;
            unsigned af[2][4], bf[8][2];
            #pragma unroll
            for (int mt = 0; mt < 2; mt++) {
                int r = warpM + mt * 16 + g;
                af[mt][0] = As[p][r][kk + t4];
                af[mt][1] = As[p][r + 8][kk + t4];
                af[mt][2] = As[p][r][kk + t4 + 4];
                af[mt][3] = As[p][r + 8][kk + t4 + 4];
            }
            #pragma unroll
            for (int nt = 0; nt < 8; nt++) {
                int ncc = warpN + nt * 8 + g;
                bf[nt][0] = Bs[p][kk + t4][ncc];
                bf[nt][1] = Bs[p][kk + t4 + 4][ncc];
            }
            #pragma unroll
            for (int mt = 0; mt < 2; mt++)
                #pragma unroll
                for (int nt = 0; nt < 8; nt++)
                    mma_tf32(c[mt][nt], af[mt], bf[nt]);
        }
        if (++p == 3) p = 0;
    }

    #pragma unroll
    for (int mt = 0; mt < 2; mt++) {
        int s0 = rowBase + warpM + mt * 16 + g;
        int s1 = s0 + 8;
        const bool st0 = (s0 < total), st1 = (s1 < total);
        const int cr0 = st0 ? g_gidx[s0] : 0;
        const int cr1 = st1 ? g_gidx[s1] : 0;
        #pragma unroll
        for (int nt = 0; nt < 8; nt++) {
            int ncc = colBase + warpN + nt * 8 + t4 * 2;
            float bx = bias[ncc], by = bias[ncc + 1];
            float2 w0 = make_float2(c[mt][nt][0] + bx, c[mt][nt][1] + by);
            float2 w1 = make_float2(c[mt][nt][2] + bx, c[mt][nt][3] + by);
            if (st0) *(float2*)(C + (size_t)cr0 * D_ + ncc) = w0;
            if (st1) *(float2*)(C + (size_t)cr1 * D_ + ncc) = w1;
        }
    }
}

// ============================================================================
// Flash attention over compacted rows; Q, K, V all DENSE compacted.
// ============================================================================
struct ASmem2 {
    unsigned Qs[64][132];
    unsigned Ks[2][64][132];
    unsigned Vs[2][64][132];
    float    Ps[64][68];
    float    row_max[64];
    float    row_sum[64];
    float    alpha[64];
};

__global__ void __launch_bounds__(256) attn_kernel()
{
    extern __shared__ char smem_raw[];
    ASmem2& s = *reinterpret_cast<ASmem2*>(smem_raw);

    const int bh = blockIdx.y;
    const int b  = bh >> 3;
    const int h  = bh & 7;
    const int cnt = g_cnt[b];
    const int off = g_off[b];
    const int rowBase = blockIdx.x * 64;
    if (rowBase >= cnt) return;
    const int nch = (cnt + 63) >> 6;

    const int tid  = threadIdx.x;
    const int w    = tid >> 5;
    const int lane = tid & 31;
    const int g    = lane >> 2;
    const int t4   = lane & 3;
    const int warpMs = (w & 3) * 16;
    const int warpNs = (w >> 2) * 32;
    const int warpNp = (w >> 2) * 64;

    const float* Qb = g_q + (size_t)off * D_ + h * HD_;
    const float* Kb = g_k + (size_t)off * D_ + h * HD_;
    const float* Vb = g_v + (size_t)off * D_ + h * HD_;

    const int lrow = tid >> 2;
    const int lcol = (tid & 3) * 4;

    const uint32_t ksB = smem_u32(&s.Ks[0][0][0]);
    const uint32_t vsB = smem_u32(&s.Vs[0][0][0]);
    const uint32_t STG_ = 64 * 132 * 4;

    {
        const int qr = (rowBase + lrow < cnt) ? (rowBase + lrow) : 0;
        #pragma unroll
        for (int i = 0; i < 8; i++) {
            int cc = lcol + 16 * i;
            float4 v = *(const float4*)(Qb + (size_t)qr * D_ + cc);
            s.Qs[lrow][cc + 0] = __float_as_uint(v.x);
            s.Qs[lrow][cc + 1] = __float_as_uint(v.y);
            s.Qs[lrow][cc + 2] = __float_as_uint(v.z);
            s.Qs[lrow][cc + 3] = __float_as_uint(v.w);
        }
    }
    if (tid < 64) {
        s.row_max[tid] = -3.0e38f;
        s.row_sum[tid] = 0.0f;
    }

    float o[8][4];
    #pragma unroll
    for (int nt = 0; nt < 8; nt++)
        #pragma unroll
        for (int i = 0; i < 4; i++) o[nt][i] = 0.0f;

    const int r0 = warpMs + g;
    const int r1 = r0 + 8;

    {
        const int kr = (lrow < cnt) ? lrow : 0;
        #pragma unroll
        for (int i = 0; i < 8; i++) {
            int cc = lcol + 16 * i;
            uint32_t offb = ((uint32_t)lrow * 132 + cc) * 4;
            cp16(ksB + offb, Kb + (size_t)kr * D_ + cc);
            cp16(vsB + offb, Vb + (size_t)kr * D_ + cc);
        }
        CP_COMMIT();
    }

    for (int c = 0; c < nch; c++) {
        const int p = c & 1;
        CP_WAIT0();
        __syncthreads();

        if (c + 1 < nch) {
            const int kb = (c + 1) * 64;
            const uint32_t pn = (c + 1) & 1;
            const int kr = (kb + lrow < cnt) ? (kb + lrow) : 0;
            #pragma unroll
            for (int i = 0; i < 8; i++) {
                int cc = lcol + 16 * i;
                uint32_t offb = pn * STG_ + ((uint32_t)lrow * 132 + cc) * 4;
                cp16(ksB + offb, Kb + (size_t)kr * D_ + cc);
                cp16(vsB + offb, Vb + (size_t)kr * D_ + cc);
            }
            CP_COMMIT();
        }

        // ---- S = Q @ K^T ----
        float sf[4][4];
        #pragma unroll
        for (int nt = 0; nt < 4; nt++)
            #pragma unroll
            for (int i = 0; i < 4; i++) sf[nt][i] = 0.0f;

        #pragma unroll
        for (int kk = 0; kk < 128; kk += 8) {
            unsigned af[4];
            af[0] = s.Qs[r0][kk + t4];
            af[1] = s.Qs[r1][kk + t4];
            af[2] = s.Qs[r0][kk + t4 + 4];
            af[3] = s.Qs[r1][kk + t4 + 4];
            #pragma unroll
            for (int nt = 0; nt < 4; nt++) {
                int kcol = warpNs + nt * 8 + g;
                unsigned bf[2];
                bf[0] = s.Ks[p][kcol][kk + t4];
                bf[1] = s.Ks[p][kcol][kk + t4 + 4];
                mma_tf32(sf[nt], af, bf);
            }
        }
        #pragma unroll
        for (int nt = 0; nt < 4; nt++) {
            int cb = warpNs + nt * 8 + t4 * 2;
            s.Ps[r0][cb]     = sf[nt][0];
            s.Ps[r0][cb + 1] = sf[nt][1];
            s.Ps[r1][cb]     = sf[nt][2];
            s.Ps[r1][cb + 1] = sf[nt][3];
        }
        __syncthreads();

        // ---- quartet softmax ----
        {
            const int r  = tid >> 2;
            const int cb = (tid & 3) * 16;
            const int kbase = c * 64 + cb;
            float m = s.row_max[r];
            float tv[16];
            float cm = -3.0e38f;
            #pragma unroll
            for (int c2 = 0; c2 < 16; c2++) {
                float v = (kbase + c2 < cnt) ? s.Ps[r][cb + c2] * SCALE_ : NEG_;
                tv[c2] = v;
                cm = fmaxf(cm, v);
            }
            cm = fmaxf(cm, __shfl_xor_sync(0xFFFFFFFFu, cm, 1));
            cm = fmaxf(cm, __shfl_xor_sync(0xFFFFFFFFu, cm, 2));
            float nm = fmaxf(m, cm);
            float al = __expf(m - nm);
            float sum = 0.0f;
            #pragma unroll
            for (int c2 = 0; c2 < 16; c2++) {
                float pp = __expf(tv[c2] - nm);
                s.Ps[r][cb + c2] = pp;
                sum += pp;
            }
            sum += __shfl_xor_sync(0xFFFFFFFFu, sum, 1);
            sum += __shfl_xor_sync(0xFFFFFFFFu, sum, 2);
            if ((tid & 3) == 0) {
                s.row_sum[r] = s.row_sum[r] * al + sum;
                s.row_max[r] = nm;
                s.alpha[r]   = al;
            }
        }
        __syncthreads();

        // ---- O = O*alpha + P @ V ----
        float al0 = s.alpha[r0], al1 = s.alpha[r1];
        #pragma unroll
        for (int nt = 0; nt < 8; nt++) {
            o[nt][0] *= al0; o[nt][1] *= al0;
            o[nt][2] *= al1; o[nt][3] *= al1;
        }
        #pragma unroll
        for (int kk = 0; kk < 64; kk += 8) {
            unsigned af[4];
            af[0] = f2tf(s.Ps[r0][kk + t4]);
            af[1] = f2tf(s.Ps[r1][kk + t4]);
            af[2] = f2tf(s.Ps[r0][kk + t4 + 4]);
            af[3] = f2tf(s.Ps[r1][kk + t4 + 4]);
            #pragma unroll
            for (int nt = 0; nt < 8; nt++) {
                int ec = warpNp + nt * 8 + g;
                unsigned bf[2];
                bf[0] = s.Vs[p][kk + t4][ec];
                bf[1] = s.Vs[p][kk + t4 + 4][ec];
                mma_tf32(o[nt], af, bf);
            }
        }
    }

    // ---- epilogue: dense compacted rows ----
    float inv0 = 1.0f / s.row_sum[r0];
    float inv1 = 1.0f / s.row_sum[r1];
    if (rowBase + r0 < cnt) {
        size_t gr = (size_t)(off + rowBase + r0) * D_;
        #pragma unroll
        for (int nt = 0; nt < 8; nt++) {
            int cc = h * HD_ + warpNp + nt * 8 + t4 * 2;
            float2 w0;
            w0.x = __uint_as_float(f2tf(o[nt][0] * inv0));
            w0.y = __uint_as_float(f2tf(o[nt][1] * inv0));
            *(float2*)(g_att + gr + cc) = w0;
        }
    }
    if (rowBase + r1 < cnt) {
        size_t gr = (size_t)(off + rowBase + r1) * D_;
        #pragma unroll
        for (int nt = 0; nt < 8; nt++) {
            int cc = h * HD_ + warpNp + nt * 8 + t4 * 2;
            float2 w1;
            w1.x = __uint_as_float(f2tf(o[nt][2] * inv1));
            w1.y = __uint_as_float(f2tf(o[nt][3] * inv1));
            *(float2*)(g_att + gr + cc) = w1;
        }
    }
}

// ============================================================================
extern "C" void kernel_launch(void* const* d_in, const int* in_sizes, int n_in,
                              void* d_out, int out_size)
{
    const float* x    = (const float*)d_in[0];
    const int*   xm   = (const int*)d_in[1];
    const float* Wq   = (const float*)d_in[2];
    const float* bq   = (const float*)d_in[3];
    const float* Wk   = (const float*)d_in[4];
    const float* bk   = (const float*)d_in[5];
    const float* Wv   = (const float*)d_in[6];
    const float* bv   = (const float*)d_in[7];
    const float* Wfc  = (const float*)d_in[8];
    const float* bfc  = (const float*)d_in[9];
    float* out = (float*)d_out;

    float *ap, *xp, *wqp, *wkp, *wvp, *wfp;
    cudaGetSymbolAddress((void**)&ap,  g_att);
    cudaGetSymbolAddress((void**)&xp,  g_x);
    cudaGetSymbolAddress((void**)&wqp, g_wq);
    cudaGetSymbolAddress((void**)&wkp, g_wk);
    cudaGetSymbolAddress((void**)&wvp, g_wv);
    cudaGetSymbolAddress((void**)&wfp, g_wf);

    cudaFuncSetAttribute(attn_kernel,
                         cudaFuncAttributeMaxDynamicSharedMemorySize,
                         (int)sizeof(ASmem2));

    // mask compaction
    scan_kernel<<<B_, N_>>>(xm);
    offset_kernel<<<1, 32>>>();
    gidx_kernel<<<B_, 256>>>();

    // operand pre-conversion to tf32
    const int XN4 = (M_TOT * D_) / 4;
    const int WN4 = (H_ * D_ * HD_) / 4;
    conv_tf32_kernel<<<(XN4 + 255) / 256, 256>>>((const float4*)x,  (float4*)xp,  XN4);
    conv_tf32_kernel<<<(WN4 + 255) / 256, 256>>>((const float4*)Wq, (float4*)wqp, WN4);
    conv_tf32_kernel<<<(WN4 + 255) / 256, 256>>>((const float4*)Wk, (float4*)wkp, WN4);
    conv_tf32_kernel<<<(WN4 + 255) / 256, 256>>>((const float4*)Wv, (float4*)wvp, WN4);
    conv_tf32_kernel<<<(WN4 + 255) / 256, 256>>>((const float4*)Wfc,(float4*)wfp, WN4);

    // fused compacted QKV projection
    qkv_gemm_kernel<<<dim3(24, 128), 256>>>(xp, wqp, wkp, wvp, bq, bk, bv);

    // masked-row path via linearity: xmean -> vmean -> outm -> broadcast
    xmean_kernel<<<dim3(8, B_), 128>>>();
    vmeanlin_kernel<<<dim3(H_, B_), 128>>>(bv);
    outm_kernel<<<dim3(8, B_), 128>>>(bfc);
    fillout_kernel<<<M_TOT, 128>>>(xm, out);

    // compacted attention (all operands dense compacted)
    attn_kernel<<<dim3(16, B_ * H_), 256, sizeof(ASmem2)>>>();

    // FC: dense compacted A, scattered C
    fc_gemm_kernel<<<dim3(8, 128), 256>>>(ap, wfp, bfc, out);
}